// round 9
// baseline (speedup 1.0000x reference)
#include <cuda_runtime.h>

// Problem constants
#define BQ   32
#define TT   512
#define DDIM 512
#define HH   8
#define HD   64
#define TEDIM 2048
#define MROWS (BQ*TT)            // 16384
#define YN ((size_t)BQ*TT*DDIM)  // 8388608
#define SN ((size_t)BQ*HH*TT*TT) // 67108864
#define WSZ (DDIM*DDIM)          // 262144

// Scratch (device globals — no allocation allowed)
__device__ float g_xn[BQ*TT*DDIM];
__device__ float g_q [BQ*TT*DDIM];
__device__ float g_k [BQ*TT*DDIM];
__device__ float g_v [BQ*TT*DDIM];   // stored TRANSPOSED: [b][h*64+d][t]
__device__ float g_y [BQ*TT*DDIM];
__device__ float g_hs[BQ*TT*DDIM];
__device__ float g_sigma[BQ*HH*TT];
__device__ float g_style[BQ*2*DDIM];
__device__ float g_wr[4*WSZ];        // tf32-rounded [Wq;Wk;Wv] (1536x512) + outW

__device__ __forceinline__ float siluf(float z){ return z / (1.f + expf(-z)); }

__device__ __forceinline__ float tf32r(float f){
    unsigned u; asm("cvt.rna.tf32.f32 %0, %1;" : "=r"(u) : "f"(f));
    return __uint_as_float(u);
}

__device__ __forceinline__ void mma8(float* c,
    unsigned a0, unsigned a1, unsigned a2, unsigned a3,
    unsigned b0, unsigned b1)
{
    asm volatile(
        "mma.sync.aligned.m16n8k8.row.col.f32.tf32.tf32.f32 "
        "{%0,%1,%2,%3}, {%4,%5,%6,%7}, {%8,%9}, {%0,%1,%2,%3};"
        : "+f"(c[0]), "+f"(c[1]), "+f"(c[2]), "+f"(c[3])
        : "r"(a0), "r"(a1), "r"(a2), "r"(a3), "r"(b0), "r"(b1));
}

__device__ __forceinline__ void cp16(unsigned dst, const void* src){
    asm volatile("cp.async.cg.shared.global [%0], [%1], 16;" :: "r"(dst), "l"(src));
}
#define CPCOMMIT() asm volatile("cp.async.commit_group;" ::: "memory")
#define CPWAIT(n)  asm volatile("cp.async.wait_group %0;" :: "n"(n) : "memory")

__device__ __forceinline__ uint4 ldmx4(unsigned a){
    uint4 r;
    asm volatile("ldmatrix.sync.aligned.m8n8.x4.shared.b16 {%0,%1,%2,%3}, [%4];"
        : "=r"(r.x), "=r"(r.y), "=r"(r.z), "=r"(r.w) : "r"(a));
    return r;
}

// ---------------------------------------------------------------------------
// filler routines (512-thread variants)
// ---------------------------------------------------------------------------
__device__ __forceinline__ void prior_slab512(long slab, float* __restrict__ prior,
                                              float* __restrict__ sfull)
{
    int tid = threadIdx.x;
    int w = tid >> 5, l = tid & 31;
    long base = slab * 32;
    #pragma unroll
    for (int i = 0; i < 2; i++){
        long row = base + w*2 + i;            // (b*H+h)*T + n
        int n = (int)(row & 511);
        float s = g_sigma[row];
        float inv2 = -1.f / (2.f * s * s);
        float coef = 0.3989422804014327f / s;
        float4 sv = make_float4(s, s, s, s);
        float4* pp = (float4*)(prior + row * TT);
        float4* sp = (float4*)(sfull + row * TT);
        #pragma unroll
        for (int j = 0; j < 4; j++){
            int c4 = l + j*32;                // float4 index 0..127
            int m = c4 * 4;
            float d0 = (float)(n - m);
            float d1 = (float)(n - (m+1));
            float d2 = (float)(n - (m+2));
            float d3 = (float)(n - (m+3));
            float4 pv;
            pv.x = __expf(d0*d0*inv2) * coef;
            pv.y = __expf(d1*d1*inv2) * coef;
            pv.z = __expf(d2*d2*inv2) * coef;
            pv.w = __expf(d3*d3*inv2) * coef;
            pp[c4] = pv;
            sp[c4] = sv;
        }
    }
}

__device__ __forceinline__ void style_part512(int sbi, const float* __restrict__ emb,
                                              const float* __restrict__ embW,
                                              const float* __restrict__ embB,
                                              float* se)
{
    int tid = threadIdx.x;
    int bb = sbi >> 1, part = sbi & 1;
    for (int i = tid; i < TEDIM; i += 512){
        float e = emb[(size_t)bb * TEDIM + i];
        se[i] = siluf(e);
    }
    __syncthreads();
    int j = part*512 + tid;                   // 0..1023
    float acc = 0.f;
    for (int k = 0; k < TEDIM; k++)
        acc += se[k] * embW[(size_t)k * (2*DDIM) + j];
    g_style[bb * (2*DDIM) + j] = acc + embB[j];
}

// ---------------------------------------------------------------------------
// LN1 + sigma, with round_w blocks packed into the same launch.
// ---------------------------------------------------------------------------
__global__ void ln1_sigma_roundw_kernel(const float* __restrict__ x,
                                        const float* __restrict__ g,
                                        const float* __restrict__ b,
                                        const float* __restrict__ Wsig,
                                        const float* __restrict__ w0,
                                        const float* __restrict__ w1,
                                        const float* __restrict__ w2,
                                        const float* __restrict__ w3)
{
    int tid = threadIdx.x;
    if (blockIdx.x >= MROWS){
        int i = (blockIdx.x - MROWS) * 256 + tid;
        g_wr[i]         = tf32r(w0[i]);
        g_wr[i +   WSZ] = tf32r(w1[i]);
        g_wr[i + 2*WSZ] = tf32r(w2[i]);
        g_wr[i + 3*WSZ] = tf32r(w3[i]);
        return;
    }
    int row = blockIdx.x;
    int warp = tid >> 5, lane = tid & 31;
    const float* xr = x + (size_t)row * DDIM;
    float x0 = xr[tid], x1 = xr[tid + 256];
    float s = x0 + x1, sq = x0*x0 + x1*x1;
    #pragma unroll
    for (int o = 16; o > 0; o >>= 1) {
        s  += __shfl_xor_sync(~0u, s,  o);
        sq += __shfl_xor_sync(~0u, sq, o);
    }
    __shared__ float sm[8], sm2[8];
    if (lane == 0) { sm[warp] = s; sm2[warp] = sq; }
    __syncthreads();
    float tot = 0.f, tot2 = 0.f;
    #pragma unroll
    for (int i = 0; i < 8; i++) { tot += sm[i]; tot2 += sm2[i]; }
    float mean = tot * (1.f / DDIM);
    float var  = tot2 * (1.f / DDIM) - mean * mean;
    float rstd = rsqrtf(var + 1e-5f);
    g_xn[(size_t)row*DDIM + tid]       = tf32r((x0 - mean) * rstd * g[tid]       + b[tid]);
    g_xn[(size_t)row*DDIM + tid + 256] = tf32r((x1 - mean) * rstd * g[tid + 256] + b[tid + 256]);

    float acc[HH];
    #pragma unroll
    for (int h = 0; h < HH; h++)
        acc[h] = x0 * Wsig[tid*HH + h] + x1 * Wsig[(tid+256)*HH + h];
    #pragma unroll
    for (int h = 0; h < HH; h++)
        #pragma unroll
        for (int o = 16; o > 0; o >>= 1)
            acc[h] += __shfl_xor_sync(~0u, acc[h], o);
    __shared__ float red[8][HH];
    if (lane == 0)
        #pragma unroll
        for (int h = 0; h < HH; h++) red[warp][h] = acc[h];
    __syncthreads();
    if (tid < HH) {
        float z = 0.f;
        #pragma unroll
        for (int w = 0; w < 8; w++) z += red[w][tid];
        float sg  = 1.f / (1.f + expf(-5.f * z)) + 1e-5f;
        float sig = exp2f(sg * 1.5849625007211562f) - 1.f;   // 3^sg - 1
        int bb = row / TT, t = row % TT;
        g_sigma[(bb*HH + tid)*TT + t] = sig;
    }
}

// ---------------------------------------------------------------------------
// tf32 NT GEMM v2 (BK=32, 3-stage cp.async, merged-QKV routing / outproj).
// ---------------------------------------------------------------------------
template<bool QKV>
__global__ void __launch_bounds__(256,2)
tf32_gemm2(const float* __restrict__ A, const float* __restrict__ Bw,
           float* __restrict__ Cq, float* __restrict__ Ck, float* __restrict__ Cv,
           const float* __restrict__ bias, const float* __restrict__ res)
{
    constexpr int ST  = 36;                // 32 + 4 pad (floats)
    constexpr int STG = 128*ST*4;          // per-operand stage bytes

    extern __shared__ float dsm[];
    const unsigned sb = (unsigned)__cvta_generic_to_shared(dsm);
    const unsigned aS = sb;
    const unsigned bS = sb + 3*STG;

    const int tid  = threadIdx.x;
    const int lane = tid & 31;
    const int wid  = tid >> 5;
    const int wm   = wid & 1;
    const int wn   = wid >> 1;
    const int g    = lane >> 2;
    const int t    = lane & 3;

    const int m0 = blockIdx.y * 128;
    const int n0 = blockIdx.x * 128;

    const int rl = tid >> 3;               // 0..31
    const int qc = tid & 7;                // 16B chunk in BK32

    const float* Ag = A  + (long)(m0 + rl) * 512 + qc*4;
    const float* Bg = Bw + (long)(n0 + rl) * 512 + qc*4;
    const unsigned dA = (unsigned)(rl*ST + qc*4) * 4;

    auto issue = [&](int st, int k0){
        unsigned ab = aS + st*STG, bb = bS + st*STG;
        #pragma unroll
        for (int e = 0; e < 4; e++){
            cp16(ab + dA + e*32*ST*4, Ag + (long)e*32*512 + k0);
            cp16(bb + dA + e*32*ST*4, Bg + (long)e*32*512 + k0);
        }
    };

    const int arow = (lane & 7) + ((lane >> 3) & 1) * 8;
    const int acol = (lane >> 4) * 4;
    const unsigned aFB = (unsigned)((wm*64 + arow)*ST + acol) * 4;
    const unsigned bFB = (unsigned)((wn*32 + (lane & 7))*ST + (lane >> 3)*4) * 4;

    float acc[4][4][4];
    #pragma unroll
    for (int i = 0; i < 4; i++)
        #pragma unroll
        for (int j = 0; j < 4; j++)
            #pragma unroll
            for (int p = 0; p < 4; p++) acc[i][j][p] = 0.f;

    issue(0, 0);  CPCOMMIT();
    issue(1, 32); CPCOMMIT();

    int buf = 0;
    for (int k0 = 0; k0 < 512; k0 += 32) {
        CPWAIT(1);
        __syncthreads();
        if (k0 + 64 < 512) {
            int nb = buf + 2; if (nb >= 3) nb -= 3;
            issue(nb, k0 + 64);
        }
        CPCOMMIT();

        const unsigned ab = aS + buf*STG;
        const unsigned bb = bS + buf*STG;

        uint4 bfr[4][2];
        #pragma unroll
        for (int nt = 0; nt < 4; nt++)
            #pragma unroll
            for (int kg = 0; kg < 2; kg++)
                bfr[nt][kg] = ldmx4(bb + bFB + (unsigned)(nt*8*ST + kg*16)*4);

        #pragma unroll
        for (int ks = 0; ks < 4; ks++) {
            #pragma unroll
            for (int mt = 0; mt < 4; mt++) {
                uint4 a = ldmx4(ab + aFB + (unsigned)(mt*16*ST + ks*8)*4);
                #pragma unroll
                for (int nt = 0; nt < 4; nt++)
                    mma8(acc[mt][nt], a.x, a.y, a.z, a.w,
                         (ks & 1) ? bfr[nt][ks>>1].z : bfr[nt][ks>>1].x,
                         (ks & 1) ? bfr[nt][ks>>1].w : bfr[nt][ks>>1].y);
            }
        }
        buf++; if (buf == 3) buf = 0;
    }

    // Epilogue
    #pragma unroll
    for (int mt = 0; mt < 4; mt++){
        #pragma unroll
        for (int nt = 0; nt < 4; nt++){
            int row = m0 + wm*64 + mt*16 + g;
            int col = n0 + wn*32 + nt*8 + 2*t;
            float v0 = acc[mt][nt][0], v1 = acc[mt][nt][1];
            float v2 = acc[mt][nt][2], v3 = acc[mt][nt][3];
            if (QKV){
                v0 = tf32r(v0); v1 = tf32r(v1); v2 = tf32r(v2); v3 = tf32r(v3);
                if (n0 < 512){
                    *(float2*)&Cq[(long)row*512 + col]     = make_float2(v0, v1);
                    *(float2*)&Cq[(long)(row+8)*512 + col] = make_float2(v2, v3);
                } else if (n0 < 1024){
                    int c2 = col - 512;
                    *(float2*)&Ck[(long)row*512 + c2]     = make_float2(v0, v1);
                    *(float2*)&Ck[(long)(row+8)*512 + c2] = make_float2(v2, v3);
                } else {
                    int vc = col - 1024;
                    long base0 = (long)(row >> 9) * (512L*512) + (row & 511);
                    Cv[base0 + (long)vc*512]         = v0;
                    Cv[base0 + (long)(vc+1)*512]     = v1;
                    Cv[base0 + 8 + (long)vc*512]     = v2;
                    Cv[base0 + 8 + (long)(vc+1)*512] = v3;
                }
            } else {
                v0 += bias[col];   v1 += bias[col+1];
                v2 += bias[col];   v3 += bias[col+1];
                v0 += res[(long)row*512 + col];
                v1 += res[(long)row*512 + col+1];
                v2 += res[(long)(row+8)*512 + col];
                v3 += res[(long)(row+8)*512 + col+1];
                *(float2*)&Cq[(long)row*512 + col]     = make_float2(v0, v1);
                *(float2*)&Cq[(long)(row+8)*512 + col] = make_float2(v2, v3);
            }
        }
    }
}

// ---------------------------------------------------------------------------
// MEGA kernel v2: BM=64 attention tiles (512 threads, 4m x 4n warps)
//   bx < 6144: bx%3==0 -> attn tile (bx/3, 0..2047); else prior slab
//              (bx/3)*2 + (bx%3 - 1)  [0..4095]
//   bx >= 6144: style part (bx-6144, 0..63)
// ---------------------------------------------------------------------------
__global__ void __launch_bounds__(512,1)
mega_attn_kernel(const float* __restrict__ Q, const float* __restrict__ Kt,
                 const float* __restrict__ Vt,
                 float* __restrict__ S, float* __restrict__ Y,
                 float* __restrict__ prior, float* __restrict__ sfull,
                 const float* __restrict__ emb,
                 const float* __restrict__ embW,
                 const float* __restrict__ embB)
{
    extern __shared__ float dsm[];
    const int tid  = threadIdx.x;
    const unsigned bx = blockIdx.x;

    if (bx >= 6144){
        style_part512((int)(bx - 6144), emb, embW, embB, dsm);
        return;
    }
    const int mod  = (int)(bx % 3);
    const int div3 = (int)(bx / 3);
    if (mod != 0){
        prior_slab512((long)div3*2 + (mod - 1), prior, sfull);
        return;
    }

    // ---------------- attention tile (64 rows) ----------------
    const int idx = div3;             // 0..2047
    const int bh = idx >> 3;          // b*8+h
    const int m0 = (idx & 7) * 64;

    constexpr int AST = 68;
    constexpr int BST = 68;
    constexpr int VST = 132;
    constexpr int SST = 132;
    const unsigned A_BYTES = 64*AST*4;            // 17408
    const unsigned B_BYTES = 128*BST*4;           // 34816

    const unsigned sb  = (unsigned)__cvta_generic_to_shared(dsm);
    const unsigned sbA = sb;
    const unsigned sbB = sb + A_BYTES;
    const unsigned sbS = sb + A_BYTES + 2*B_BYTES;       // series chunk 64x132
    float* red = dsm + (A_BYTES + 2*B_BYTES)/4 + 64*SST; // [64][4]

    const int lane = tid & 31;
    const int wid  = tid >> 5;        // 0..15
    const int wm   = wid & 3;         // 4 m-warps (16 rows each)
    const int wn   = wid >> 2;        // 4 n-warps
    const int g    = lane >> 2;
    const int t    = lane & 3;

    const int b  = bh >> 3, h = bh & 7;

    const float* Qb = Q + ((long)b*512 + m0)*512 + h*64;
    const float* Kb = Kt + ((long)b*512)*512 + h*64;
    const float* Vb = Vt + (long)b*(512L*512) + (long)h*64*512; // [64 d][512 t]
    float* Sb = S + ((long)bh*512 + m0)*512;
    float* Yb = Y + ((long)b*512)*512 + h*64;

    const int arow = (lane & 7) + ((lane >> 3) & 1) * 8;
    const int acol = (lane >> 4) * 4;
    const unsigned aF  = sbA + (unsigned)((wm*16 + arow)*AST + acol) * 4;
    const unsigned bF  = (unsigned)((wn*32 + (lane & 7))*BST + (lane >> 3)*4) * 4;
    const unsigned sF  = sbS + (unsigned)((wm*16 + arow)*SST + acol) * 4;
    const unsigned vF  = (unsigned)((wn*16 + (lane & 7))*VST + (lane >> 3)*4) * 4;

    auto issueB = [&](int chunk, int bufb){
        unsigned dst = sbB + (unsigned)bufb * B_BYTES;
        const float* src = Kb + (long)(chunk*128)*512;
        #pragma unroll
        for (int e = 0; e < 4; e++){
            int idx2 = tid + 512*e;           // 0..2047
            int r = idx2 >> 4, c4 = idx2 & 15;
            cp16(dst + (unsigned)(r*BST + c4*4)*4, src + (long)r*512 + c4*4);
        }
    };
    auto issueV = [&](int chunk, int bufb){
        unsigned dst = sbB + (unsigned)bufb * B_BYTES;
        #pragma unroll
        for (int e = 0; e < 4; e++){
            int idx2 = tid + 512*e;           // 0..2047
            int r  = idx2 >> 5;               // 0..63  (d-row)
            int qc = idx2 & 31;               // 0..31  (16B chunk of 128 t-cols)
            cp16(dst + (unsigned)(r*VST + qc*4)*4,
                 Vb + (long)r*512 + chunk*128 + qc*4);
        }
    };

    // group 0: Q tile (64 rows) + K chunk 0
    {
        #pragma unroll
        for (int e = 0; e < 2; e++){
            int idx2 = tid + 512*e;           // 0..1023
            int r = idx2 >> 4, c4 = idx2 & 15;
            cp16(sbA + (unsigned)(r*AST + c4*4)*4, Qb + (long)r*512 + c4*4);
        }
        issueB(0, 0);
        CPCOMMIT();
    }

    float acc[4][4][4];
    #pragma unroll
    for (int c = 0; c < 4; c++)
        #pragma unroll
        for (int nt = 0; nt < 4; nt++)
            #pragma unroll
            for (int p = 0; p < 4; p++) acc[c][nt][p] = 0.f;

    for (int c = 0; c < 4; c++){
        CPWAIT(0);
        __syncthreads();
        if (c + 1 < 4) issueB(c + 1, (c + 1) & 1);
        CPCOMMIT();

        const unsigned bb2 = sbB + (unsigned)(c & 1) * B_BYTES;
        #pragma unroll
        for (int kg = 0; kg < 4; kg++){
            uint4 a0 = ldmx4(aF + (unsigned)(kg*16 + 0)*4);
            uint4 a1 = ldmx4(aF + (unsigned)(kg*16 + 8)*4);
            #pragma unroll
            for (int nt = 0; nt < 4; nt++){
                uint4 bv = ldmx4(bb2 + bF + (unsigned)(nt*8*BST + kg*16)*4);
                mma8(acc[c][nt], a0.x, a0.y, a0.z, a0.w, bv.x, bv.y);
                mma8(acc[c][nt], a1.x, a1.y, a1.z, a1.w, bv.z, bv.w);
            }
        }
        __syncthreads();
    }

    // prefetch V chunks 0,1 into the two (now free) B buffers
    issueV(0, 0); CPCOMMIT();
    issueV(1, 1); CPCOMMIT();

    // softmax
    #pragma unroll
    for (int c = 0; c < 4; c++)
        #pragma unroll
        for (int nt = 0; nt < 4; nt++)
            #pragma unroll
            for (int p = 0; p < 4; p++) acc[c][nt][p] *= (1.f/64.f);

    const int r0 = wm*16 + g, r1 = r0 + 8;

    float mx0 = -1e30f, mx1 = -1e30f;
    #pragma unroll
    for (int c = 0; c < 4; c++)
        #pragma unroll
        for (int nt = 0; nt < 4; nt++){
            mx0 = fmaxf(mx0, fmaxf(acc[c][nt][0], acc[c][nt][1]));
            mx1 = fmaxf(mx1, fmaxf(acc[c][nt][2], acc[c][nt][3]));
        }
    #pragma unroll
    for (int o = 1; o <= 2; o <<= 1){
        mx0 = fmaxf(mx0, __shfl_xor_sync(~0u, mx0, o));
        mx1 = fmaxf(mx1, __shfl_xor_sync(~0u, mx1, o));
    }
    if (t == 0){ red[r0*4 + wn] = mx0; red[r1*4 + wn] = mx1; }
    __syncthreads();
    float rm0 = fmaxf(fmaxf(red[r0*4+0], red[r0*4+1]), fmaxf(red[r0*4+2], red[r0*4+3]));
    float rm1 = fmaxf(fmaxf(red[r1*4+0], red[r1*4+1]), fmaxf(red[r1*4+2], red[r1*4+3]));
    __syncthreads();

    float s0 = 0.f, s1 = 0.f;
    #pragma unroll
    for (int c = 0; c < 4; c++)
        #pragma unroll
        for (int nt = 0; nt < 4; nt++){
            acc[c][nt][0] = __expf(acc[c][nt][0] - rm0);
            acc[c][nt][1] = __expf(acc[c][nt][1] - rm0);
            acc[c][nt][2] = __expf(acc[c][nt][2] - rm1);
            acc[c][nt][3] = __expf(acc[c][nt][3] - rm1);
            s0 += acc[c][nt][0] + acc[c][nt][1];
            s1 += acc[c][nt][2] + acc[c][nt][3];
        }
    #pragma unroll
    for (int o = 1; o <= 2; o <<= 1){
        s0 += __shfl_xor_sync(~0u, s0, o);
        s1 += __shfl_xor_sync(~0u, s1, o);
    }
    if (t == 0){ red[r0*4 + wn] = s0; red[r1*4 + wn] = s1; }
    __syncthreads();
    float inv0 = 1.f / (red[r0*4+0] + red[r0*4+1] + red[r0*4+2] + red[r0*4+3]);
    float inv1 = 1.f / (red[r1*4+0] + red[r1*4+1] + red[r1*4+2] + red[r1*4+3]);

    // AV: per 128-col chunk stage tf32(series) in smem, mma against V chunk
    float yacc[2][4];
    #pragma unroll
    for (int nt = 0; nt < 2; nt++)
        #pragma unroll
        for (int p = 0; p < 4; p++) yacc[nt][p] = 0.f;

    float* Srow0 = dsm + (A_BYTES + 2*B_BYTES)/4;
    float* p0 = Sb + (long)r0*512;
    float* p1 = Sb + (long)r1*512;

    #pragma unroll
    for (int c = 0; c < 4; c++){
        #pragma unroll
        for (int nt = 0; nt < 4; nt++){
            int colc = wn*32 + nt*8 + 2*t;
            float n00 = acc[c][nt][0]*inv0, n01 = acc[c][nt][1]*inv0;
            float n10 = acc[c][nt][2]*inv1, n11 = acc[c][nt][3]*inv1;
            Srow0[r0*SST + colc]   = tf32r(n00);
            Srow0[r0*SST + colc+1] = tf32r(n01);
            Srow0[r1*SST + colc]   = tf32r(n10);
            Srow0[r1*SST + colc+1] = tf32r(n11);
            *(float2*)&p0[c*128 + colc] = make_float2(n00, n01);
            *(float2*)&p1[c*128 + colc] = make_float2(n10, n11);
        }
        if (c < 3) { CPWAIT(1); } else { CPWAIT(0); }
        __syncthreads();

        const unsigned vb = sbB + (unsigned)(c & 1) * B_BYTES;
        #pragma unroll
        for (int kg = 0; kg < 8; kg++){
            uint4 a0 = ldmx4(sF + (unsigned)(kg*16 + 0)*4);
            uint4 a1 = ldmx4(sF + (unsigned)(kg*16 + 8)*4);
            #pragma unroll
            for (int nt = 0; nt < 2; nt++){
                uint4 bv = ldmx4(vb + vF + (unsigned)(nt*8*VST + kg*16)*4);
                mma8(yacc[nt], a0.x, a0.y, a0.z, a0.w, bv.x, bv.y);
                mma8(yacc[nt], a1.x, a1.y, a1.z, a1.w, bv.z, bv.w);
            }
        }
        __syncthreads();
        if (c + 2 < 4){ issueV(c + 2, c & 1); }
        CPCOMMIT();
    }

    // write y tile
    #pragma unroll
    for (int nt = 0; nt < 2; nt++){
        int col = wn*16 + nt*8 + 2*t;
        int rowA = m0 + r0, rowB = m0 + r1;
        *(float2*)&Yb[(long)rowA*512 + col] = make_float2(yacc[nt][0], yacc[nt][1]);
        *(float2*)&Yb[(long)rowB*512 + col] = make_float2(yacc[nt][2], yacc[nt][3]);
    }
}

// ---------------------------------------------------------------------------
// LN2 + scale/shift + silu (hs stored tf32-rounded)
// ---------------------------------------------------------------------------
__global__ void ln2_style_kernel(const float* __restrict__ g,
                                 const float* __restrict__ b)
{
    int row = blockIdx.x;
    int tid = threadIdx.x;
    int warp = tid >> 5, lane = tid & 31;
    int bb = row / TT;
    const float* yr = g_y + (size_t)row * DDIM;
    float x0 = yr[tid], x1 = yr[tid + 256];
    float s = x0 + x1, sq = x0*x0 + x1*x1;
    #pragma unroll
    for (int o = 16; o > 0; o >>= 1) {
        s  += __shfl_xor_sync(~0u, s,  o);
        sq += __shfl_xor_sync(~0u, sq, o);
    }
    __shared__ float sm[8], sm2[8];
    if (lane == 0) { sm[warp] = s; sm2[warp] = sq; }
    __syncthreads();
    float tot = 0.f, tot2 = 0.f;
    #pragma unroll
    for (int i = 0; i < 8; i++) { tot += sm[i]; tot2 += sm2[i]; }
    float mean = tot * (1.f / DDIM);
    float var  = tot2 * (1.f / DDIM) - mean * mean;
    float rstd = rsqrtf(var + 1e-5f);
    float n0 = (x0 - mean) * rstd * g[tid]       + b[tid];
    float n1 = (x1 - mean) * rstd * g[tid + 256] + b[tid + 256];
    const float* st = g_style + bb * (2*DDIM);
    float h0 = n0 * (1.f + st[tid])       + st[512 + tid];
    float h1 = n1 * (1.f + st[tid + 256]) + st[512 + tid + 256];
    g_hs[(size_t)row*DDIM + tid]       = tf32r(siluf(h0));
    g_hs[(size_t)row*DDIM + tid + 256] = tf32r(siluf(h1));
}

// ---------------------------------------------------------------------------
extern "C" void kernel_launch(void* const* d_in, const int* in_sizes, int n_in,
                              void* d_out, int out_size)
{
    const float* x    = (const float*)d_in[0];
    const float* emb  = (const float*)d_in[1];
    const float* Wq   = (const float*)d_in[2];
    const float* Wk   = (const float*)d_in[3];
    const float* Wv   = (const float*)d_in[4];
    const float* Wsig = (const float*)d_in[5];
    const float* ln1g = (const float*)d_in[6];
    const float* ln1b = (const float*)d_in[7];
    const float* embW = (const float*)d_in[8];
    const float* embB = (const float*)d_in[9];
    const float* ln2g = (const float*)d_in[10];
    const float* ln2b = (const float*)d_in[11];
    const float* outW = (const float*)d_in[12];
    const float* outB = (const float*)d_in[13];

    float* out    = (float*)d_out;
    float* outY   = out;
    float* outS   = out + YN;
    float* outP   = outS + SN;
    float* outSig = outP + SN;

    float *pxn, *pq, *pk, *pv, *py, *phs, *pwr;
    cudaGetSymbolAddress((void**)&pxn, g_xn);
    cudaGetSymbolAddress((void**)&pq,  g_q);
    cudaGetSymbolAddress((void**)&pk,  g_k);
    cudaGetSymbolAddress((void**)&pv,  g_v);
    cudaGetSymbolAddress((void**)&py,  g_y);
    cudaGetSymbolAddress((void**)&phs, g_hs);
    cudaGetSymbolAddress((void**)&pwr, g_wr);

    const int SMG  = 3*2*128*36*4;                           // 110592
    const int SMF2 = 64*68*4 + 2*128*68*4 + 64*132*4 + 1024; // 121856

    cudaFuncSetAttribute(tf32_gemm2<true >, cudaFuncAttributeMaxDynamicSharedMemorySize, SMG);
    cudaFuncSetAttribute(tf32_gemm2<false>, cudaFuncAttributeMaxDynamicSharedMemorySize, SMG);
    cudaFuncSetAttribute(mega_attn_kernel,  cudaFuncAttributeMaxDynamicSharedMemorySize, SMF2);

    // 1) LN1 + sigma + weight pre-round (packed)
    ln1_sigma_roundw_kernel<<<MROWS + WSZ/256, 256>>>(
        x, ln1g, ln1b, Wsig, Wq, Wk, Wv, outW);

    // 2) merged QKV projection (one launch, per-block routing)
    tf32_gemm2<true><<<dim3(12, MROWS/128), 256, SMG>>>(
        pxn, pwr, pq, pk, pv, nullptr, nullptr);

    // 3) MEGA v2: BM=64 attention + prior (1:2) + style
    mega_attn_kernel<<<6144 + 64, 512, SMF2>>>(
        pq, pk, pv, outS, py, outP, outSig, emb, embW, embB);

    // 4) LN2 + style + silu
    ln2_style_kernel<<<MROWS, 256>>>(ln2g, ln2b);

    // 5) y_out = x + silu_h @ out_W^T + out_b
    tf32_gemm2<false><<<dim3(4, MROWS/128), 256, SMG>>>(
        phs, pwr + 3*WSZ, outY, nullptr, nullptr, outB, x);
}

// round 10
// speedup vs baseline: 1.0571x; 1.0571x over previous
#include <cuda_runtime.h>

// Problem constants
#define BQ   32
#define TT   512
#define DDIM 512
#define HH   8
#define HD   64
#define TEDIM 2048
#define MROWS (BQ*TT)            // 16384
#define YN ((size_t)BQ*TT*DDIM)  // 8388608
#define SN ((size_t)BQ*HH*TT*TT) // 67108864
#define WSZ (DDIM*DDIM)          // 262144

// Scratch (device globals — no allocation allowed)
__device__ float g_xn[BQ*TT*DDIM];
__device__ float g_q [BQ*TT*DDIM];
__device__ float g_k [BQ*TT*DDIM];
__device__ float g_v [BQ*TT*DDIM];   // stored TRANSPOSED: [b][h*64+d][t]
__device__ float g_y [BQ*TT*DDIM];
__device__ float g_hs[BQ*TT*DDIM];
__device__ float g_sigma[BQ*HH*TT];
__device__ float g_style[BQ*2*DDIM];
__device__ float g_wr[4*WSZ];        // tf32-rounded [Wq;Wk;Wv] (1536x512) + outW

__device__ __forceinline__ float siluf(float z){ return z / (1.f + expf(-z)); }

__device__ __forceinline__ float tf32r(float f){
    unsigned u; asm("cvt.rna.tf32.f32 %0, %1;" : "=r"(u) : "f"(f));
    return __uint_as_float(u);
}

__device__ __forceinline__ void mma8(float* c,
    unsigned a0, unsigned a1, unsigned a2, unsigned a3,
    unsigned b0, unsigned b1)
{
    asm volatile(
        "mma.sync.aligned.m16n8k8.row.col.f32.tf32.tf32.f32 "
        "{%0,%1,%2,%3}, {%4,%5,%6,%7}, {%8,%9}, {%0,%1,%2,%3};"
        : "+f"(c[0]), "+f"(c[1]), "+f"(c[2]), "+f"(c[3])
        : "r"(a0), "r"(a1), "r"(a2), "r"(a3), "r"(b0), "r"(b1));
}

__device__ __forceinline__ void cp16(unsigned dst, const void* src){
    asm volatile("cp.async.cg.shared.global [%0], [%1], 16;" :: "r"(dst), "l"(src));
}
#define CPCOMMIT() asm volatile("cp.async.commit_group;" ::: "memory")
#define CPWAIT(n)  asm volatile("cp.async.wait_group %0;" :: "n"(n) : "memory")

__device__ __forceinline__ uint4 ldmx4(unsigned a){
    uint4 r;
    asm volatile("ldmatrix.sync.aligned.m8n8.x4.shared.b16 {%0,%1,%2,%3}, [%4];"
        : "=r"(r.x), "=r"(r.y), "=r"(r.z), "=r"(r.w) : "r"(a));
    return r;
}

// ---------------------------------------------------------------------------
// LN1 + sigma, with round_w blocks packed into the same launch.
// blocks [0,16384): LN1 rows.  blocks [16384,17408): weight pre-round.
// ---------------------------------------------------------------------------
__global__ void ln1_sigma_roundw_kernel(const float* __restrict__ x,
                                        const float* __restrict__ g,
                                        const float* __restrict__ b,
                                        const float* __restrict__ Wsig,
                                        const float* __restrict__ w0,
                                        const float* __restrict__ w1,
                                        const float* __restrict__ w2,
                                        const float* __restrict__ w3)
{
    int tid = threadIdx.x;
    if (blockIdx.x >= MROWS){
        int i = (blockIdx.x - MROWS) * 256 + tid;
        g_wr[i]         = tf32r(w0[i]);
        g_wr[i +   WSZ] = tf32r(w1[i]);
        g_wr[i + 2*WSZ] = tf32r(w2[i]);
        g_wr[i + 3*WSZ] = tf32r(w3[i]);
        return;
    }
    int row = blockIdx.x;
    int warp = tid >> 5, lane = tid & 31;
    const float* xr = x + (size_t)row * DDIM;
    float x0 = xr[tid], x1 = xr[tid + 256];
    float s = x0 + x1, sq = x0*x0 + x1*x1;
    #pragma unroll
    for (int o = 16; o > 0; o >>= 1) {
        s  += __shfl_xor_sync(~0u, s,  o);
        sq += __shfl_xor_sync(~0u, sq, o);
    }
    __shared__ float sm[8], sm2[8];
    if (lane == 0) { sm[warp] = s; sm2[warp] = sq; }
    __syncthreads();
    float tot = 0.f, tot2 = 0.f;
    #pragma unroll
    for (int i = 0; i < 8; i++) { tot += sm[i]; tot2 += sm2[i]; }
    float mean = tot * (1.f / DDIM);
    float var  = tot2 * (1.f / DDIM) - mean * mean;
    float rstd = rsqrtf(var + 1e-5f);
    g_xn[(size_t)row*DDIM + tid]       = tf32r((x0 - mean) * rstd * g[tid]       + b[tid]);
    g_xn[(size_t)row*DDIM + tid + 256] = tf32r((x1 - mean) * rstd * g[tid + 256] + b[tid + 256]);

    float acc[HH];
    #pragma unroll
    for (int h = 0; h < HH; h++)
        acc[h] = x0 * Wsig[tid*HH + h] + x1 * Wsig[(tid+256)*HH + h];
    #pragma unroll
    for (int h = 0; h < HH; h++)
        #pragma unroll
        for (int o = 16; o > 0; o >>= 1)
            acc[h] += __shfl_xor_sync(~0u, acc[h], o);
    __shared__ float red[8][HH];
    if (lane == 0)
        #pragma unroll
        for (int h = 0; h < HH; h++) red[warp][h] = acc[h];
    __syncthreads();
    if (tid < HH) {
        float z = 0.f;
        #pragma unroll
        for (int w = 0; w < 8; w++) z += red[w][tid];
        float sg  = 1.f / (1.f + expf(-5.f * z)) + 1e-5f;
        float sig = exp2f(sg * 1.5849625007211562f) - 1.f;   // 3^sg - 1
        int bb = row / TT, t = row % TT;
        g_sigma[(bb*HH + tid)*TT + t] = sig;
    }
}

// ---------------------------------------------------------------------------
// tf32 NT GEMM v2 (BK=32, 3-stage cp.async, merged-QKV routing / outproj).
// ---------------------------------------------------------------------------
template<bool QKV>
__global__ void __launch_bounds__(256,2)
tf32_gemm2(const float* __restrict__ A, const float* __restrict__ Bw,
           float* __restrict__ Cq, float* __restrict__ Ck, float* __restrict__ Cv,
           const float* __restrict__ bias, const float* __restrict__ res)
{
    constexpr int ST  = 36;                // 32 + 4 pad (floats)
    constexpr int STG = 128*ST*4;          // per-operand stage bytes

    extern __shared__ float dsm[];
    const unsigned sb = (unsigned)__cvta_generic_to_shared(dsm);
    const unsigned aS = sb;
    const unsigned bS = sb + 3*STG;

    const int tid  = threadIdx.x;
    const int lane = tid & 31;
    const int wid  = tid >> 5;
    const int wm   = wid & 1;
    const int wn   = wid >> 1;
    const int g    = lane >> 2;
    const int t    = lane & 3;

    const int m0 = blockIdx.y * 128;
    const int n0 = blockIdx.x * 128;

    const int rl = tid >> 3;               // 0..31
    const int qc = tid & 7;                // 16B chunk in BK32

    const float* Ag = A  + (long)(m0 + rl) * 512 + qc*4;
    const float* Bg = Bw + (long)(n0 + rl) * 512 + qc*4;
    const unsigned dA = (unsigned)(rl*ST + qc*4) * 4;

    auto issue = [&](int st, int k0){
        unsigned ab = aS + st*STG, bb = bS + st*STG;
        #pragma unroll
        for (int e = 0; e < 4; e++){
            cp16(ab + dA + e*32*ST*4, Ag + (long)e*32*512 + k0);
            cp16(bb + dA + e*32*ST*4, Bg + (long)e*32*512 + k0);
        }
    };

    const int arow = (lane & 7) + ((lane >> 3) & 1) * 8;
    const int acol = (lane >> 4) * 4;
    const unsigned aFB = (unsigned)((wm*64 + arow)*ST + acol) * 4;
    const unsigned bFB = (unsigned)((wn*32 + (lane & 7))*ST + (lane >> 3)*4) * 4;

    float acc[4][4][4];
    #pragma unroll
    for (int i = 0; i < 4; i++)
        #pragma unroll
        for (int j = 0; j < 4; j++)
            #pragma unroll
            for (int p = 0; p < 4; p++) acc[i][j][p] = 0.f;

    issue(0, 0);  CPCOMMIT();
    issue(1, 32); CPCOMMIT();

    int buf = 0;
    for (int k0 = 0; k0 < 512; k0 += 32) {
        CPWAIT(1);
        __syncthreads();
        if (k0 + 64 < 512) {
            int nb = buf + 2; if (nb >= 3) nb -= 3;
            issue(nb, k0 + 64);
        }
        CPCOMMIT();

        const unsigned ab = aS + buf*STG;
        const unsigned bb = bS + buf*STG;

        uint4 bfr[4][2];
        #pragma unroll
        for (int nt = 0; nt < 4; nt++)
            #pragma unroll
            for (int kg = 0; kg < 2; kg++)
                bfr[nt][kg] = ldmx4(bb + bFB + (unsigned)(nt*8*ST + kg*16)*4);

        #pragma unroll
        for (int ks = 0; ks < 4; ks++) {
            #pragma unroll
            for (int mt = 0; mt < 4; mt++) {
                uint4 a = ldmx4(ab + aFB + (unsigned)(mt*16*ST + ks*8)*4);
                #pragma unroll
                for (int nt = 0; nt < 4; nt++)
                    mma8(acc[mt][nt], a.x, a.y, a.z, a.w,
                         (ks & 1) ? bfr[nt][ks>>1].z : bfr[nt][ks>>1].x,
                         (ks & 1) ? bfr[nt][ks>>1].w : bfr[nt][ks>>1].y);
            }
        }
        buf++; if (buf == 3) buf = 0;
    }

    // Epilogue
    #pragma unroll
    for (int mt = 0; mt < 4; mt++){
        #pragma unroll
        for (int nt = 0; nt < 4; nt++){
            int row = m0 + wm*64 + mt*16 + g;
            int col = n0 + wn*32 + nt*8 + 2*t;
            float v0 = acc[mt][nt][0], v1 = acc[mt][nt][1];
            float v2 = acc[mt][nt][2], v3 = acc[mt][nt][3];
            if (QKV){
                v0 = tf32r(v0); v1 = tf32r(v1); v2 = tf32r(v2); v3 = tf32r(v3);
                if (n0 < 512){
                    *(float2*)&Cq[(long)row*512 + col]     = make_float2(v0, v1);
                    *(float2*)&Cq[(long)(row+8)*512 + col] = make_float2(v2, v3);
                } else if (n0 < 1024){
                    int c2 = col - 512;
                    *(float2*)&Ck[(long)row*512 + c2]     = make_float2(v0, v1);
                    *(float2*)&Ck[(long)(row+8)*512 + c2] = make_float2(v2, v3);
                } else {
                    int vc = col - 1024;
                    long base0 = (long)(row >> 9) * (512L*512) + (row & 511);
                    Cv[base0 + (long)vc*512]         = v0;
                    Cv[base0 + (long)(vc+1)*512]     = v1;
                    Cv[base0 + 8 + (long)vc*512]     = v2;
                    Cv[base0 + 8 + (long)(vc+1)*512] = v3;
                }
            } else {
                v0 += bias[col];   v1 += bias[col+1];
                v2 += bias[col];   v3 += bias[col+1];
                v0 += res[(long)row*512 + col];
                v1 += res[(long)row*512 + col+1];
                v2 += res[(long)(row+8)*512 + col];
                v3 += res[(long)(row+8)*512 + col+1];
                *(float2*)&Cq[(long)row*512 + col]     = make_float2(v0, v1);
                *(float2*)&Cq[(long)(row+8)*512 + col] = make_float2(v2, v3);
            }
        }
    }
}

// ---------------------------------------------------------------------------
// MEGA kernel: attention tiles + prior fill + style GEMV in ONE launch.
//   blocks [0,8192) even: attention tile idx = bx>>1 (bh = idx>>4, m0=(idx&15)*32)
//   blocks [0,8192) odd : prior slab idx = bx>>1 (32 rows each)
//   blocks [8192,8320)  : style (sb = bx-8192; bb = sb>>2, part = sb&3)
// QK loop: redundant trailing barrier removed (head barrier of next iter
// already orders buffer reuse); one barrier re-added after the loop to
// protect the V-prefetch overwrite of buffer 1.
// ---------------------------------------------------------------------------
__global__ void __launch_bounds__(256,2)
mega_attn_kernel(const float* __restrict__ Q, const float* __restrict__ Kt,
                 const float* __restrict__ Vt,
                 float* __restrict__ S, float* __restrict__ Y,
                 float* __restrict__ prior, float* __restrict__ sfull,
                 const float* __restrict__ emb,
                 const float* __restrict__ embW,
                 const float* __restrict__ embB)
{
    extern __shared__ float dsm[];
    const int tid  = threadIdx.x;
    const unsigned bx = blockIdx.x;

    // ---------------- style blocks ----------------
    if (bx >= 8192){
        int sb = bx - 8192;
        int bb = sb >> 2, part = sb & 3;
        float* se = dsm;
        for (int i = tid; i < TEDIM; i += 256){
            float e = emb[(size_t)bb * TEDIM + i];
            se[i] = siluf(e);
        }
        __syncthreads();
        int j = part*256 + tid;
        float acc = 0.f;
        for (int k = 0; k < TEDIM; k++)
            acc += se[k] * embW[(size_t)k * (2*DDIM) + j];
        g_style[bb * (2*DDIM) + j] = acc + embB[j];
        return;
    }

    // ---------------- prior blocks ----------------
    if (bx & 1){
        long base = (long)(bx >> 1) * 32;         // first row of 32-row slab
        int w = tid >> 5, l = tid & 31;
        #pragma unroll
        for (int i = 0; i < 4; i++){
            long row = base + w*4 + i;            // (b*H+h)*T + n
            int n = (int)(row & 511);
            float s = g_sigma[row];
            float inv2 = -1.f / (2.f * s * s);
            float coef = 0.3989422804014327f / s;
            float4 sv = make_float4(s, s, s, s);
            float4* pp = (float4*)(prior + row * TT);
            float4* sp = (float4*)(sfull + row * TT);
            #pragma unroll
            for (int j = 0; j < 4; j++){
                int c4 = l + j*32;                // float4 index 0..127
                int m = c4 * 4;
                float d0 = (float)(n - m);
                float d1 = (float)(n - (m+1));
                float d2 = (float)(n - (m+2));
                float d3 = (float)(n - (m+3));
                float4 pv;
                pv.x = __expf(d0*d0*inv2) * coef;
                pv.y = __expf(d1*d1*inv2) * coef;
                pv.z = __expf(d2*d2*inv2) * coef;
                pv.w = __expf(d3*d3*inv2) * coef;
                pp[c4] = pv;
                sp[c4] = sv;
            }
        }
        return;
    }

    // ---------------- attention blocks ----------------
    const int idx = bx >> 1;
    const int bh = idx >> 4;          // b*8+h
    const int m0 = (idx & 15) * 32;

    constexpr int AST = 68;
    constexpr int BST = 68;
    constexpr int VST = 132;
    constexpr int SST = 132;
    const unsigned A_BYTES = 32*AST*4;            // 8704
    const unsigned B_BYTES = 128*BST*4;           // 34816

    const unsigned sb  = (unsigned)__cvta_generic_to_shared(dsm);
    const unsigned sbA = sb;
    const unsigned sbB = sb + A_BYTES;
    const unsigned sbS = sb + A_BYTES + 2*B_BYTES;       // series chunk 32x132
    float* red = dsm + (A_BYTES + 2*B_BYTES)/4 + 32*SST; // [32][4]

    const int lane = tid & 31;
    const int wid  = tid >> 5;
    const int wm   = wid & 1;
    const int wn   = wid >> 1;        // 0..3
    const int g    = lane >> 2;
    const int t    = lane & 3;

    const int b  = bh >> 3, h = bh & 7;

    const float* Qb = Q + ((long)b*512 + m0)*512 + h*64;
    const float* Kb = Kt + ((long)b*512)*512 + h*64;
    const float* Vb = Vt + (long)b*(512L*512) + (long)h*64*512; // [64 d][512 t]
    float* Sb = S + ((long)bh*512 + m0)*512;
    float* Yb = Y + ((long)b*512)*512 + h*64;

    const int arow = (lane & 7) + ((lane >> 3) & 1) * 8;
    const int acol = (lane >> 4) * 4;
    const unsigned aF  = sbA + (unsigned)((wm*16 + arow)*AST + acol) * 4;
    const unsigned bF  = (unsigned)((wn*32 + (lane & 7))*BST + (lane >> 3)*4) * 4;
    const unsigned sF  = sbS + (unsigned)((wm*16 + arow)*SST + acol) * 4;
    const unsigned vF  = (unsigned)((wn*16 + (lane & 7))*VST + (lane >> 3)*4) * 4;

    auto issueB = [&](int chunk, int bufb){
        unsigned dst = sbB + (unsigned)bufb * B_BYTES;
        const float* src = Kb + (long)(chunk*128)*512;
        #pragma unroll
        for (int e = 0; e < 8; e++){
            int idx2 = tid + 256*e;
            int r = idx2 >> 4, c4 = idx2 & 15;
            cp16(dst + (unsigned)(r*BST + c4*4)*4, src + (long)r*512 + c4*4);
        }
    };
    auto issueV = [&](int chunk, int bufb){
        unsigned dst = sbB + (unsigned)bufb * B_BYTES;
        #pragma unroll
        for (int e = 0; e < 8; e++){
            int idx2 = tid + 256*e;       // 0..2047
            int r  = idx2 >> 5;           // 0..63  (d-row)
            int qc = idx2 & 31;           // 0..31  (16B chunk of 128 t-cols)
            cp16(dst + (unsigned)(r*VST + qc*4)*4,
                 Vb + (long)r*512 + chunk*128 + qc*4);
        }
    };

    // group 0: Q tile + K chunk 0
    {
        #pragma unroll
        for (int e = 0; e < 2; e++){
            int idx2 = tid + 256*e;
            int r = idx2 >> 4, c4 = idx2 & 15;
            cp16(sbA + (unsigned)(r*AST + c4*4)*4, Qb + (long)r*512 + c4*4);
        }
        issueB(0, 0);
        CPCOMMIT();
    }

    float acc[4][4][4];
    #pragma unroll
    for (int c = 0; c < 4; c++)
        #pragma unroll
        for (int nt = 0; nt < 4; nt++)
            #pragma unroll
            for (int p = 0; p < 4; p++) acc[c][nt][p] = 0.f;

    for (int c = 0; c < 4; c++){
        CPWAIT(0);
        __syncthreads();                  // orders prior-iter mma before refill
        if (c + 1 < 4) issueB(c + 1, (c + 1) & 1);
        CPCOMMIT();

        const unsigned bb2 = sbB + (unsigned)(c & 1) * B_BYTES;
        #pragma unroll
        for (int kg = 0; kg < 4; kg++){
            uint4 a0 = ldmx4(aF + (unsigned)(kg*16 + 0)*4);
            uint4 a1 = ldmx4(aF + (unsigned)(kg*16 + 8)*4);
            #pragma unroll
            for (int nt = 0; nt < 4; nt++){
                uint4 bv = ldmx4(bb2 + bF + (unsigned)(nt*8*BST + kg*16)*4);
                mma8(acc[c][nt], a0.x, a0.y, a0.z, a0.w, bv.x, bv.y);
                mma8(acc[c][nt], a1.x, a1.y, a1.z, a1.w, bv.z, bv.w);
            }
        }
        // trailing barrier removed — next iteration's head barrier covers it
    }
    __syncthreads();                      // protect V prefetch overwriting buf 1

    // prefetch V chunks 0,1 into the two (now free) B buffers
    issueV(0, 0); CPCOMMIT();
    issueV(1, 1); CPCOMMIT();

    // softmax: scale, max, exp, sum (overlaps V prefetch)
    #pragma unroll
    for (int c = 0; c < 4; c++)
        #pragma unroll
        for (int nt = 0; nt < 4; nt++)
            #pragma unroll
            for (int p = 0; p < 4; p++) acc[c][nt][p] *= (1.f/64.f);

    const int r0 = wm*16 + g, r1 = r0 + 8;

    float mx0 = -1e30f, mx1 = -1e30f;
    #pragma unroll
    for (int c = 0; c < 4; c++)
        #pragma unroll
        for (int nt = 0; nt < 4; nt++){
            mx0 = fmaxf(mx0, fmaxf(acc[c][nt][0], acc[c][nt][1]));
            mx1 = fmaxf(mx1, fmaxf(acc[c][nt][2], acc[c][nt][3]));
        }
    #pragma unroll
    for (int o = 1; o <= 2; o <<= 1){
        mx0 = fmaxf(mx0, __shfl_xor_sync(~0u, mx0, o));
        mx1 = fmaxf(mx1, __shfl_xor_sync(~0u, mx1, o));
    }
    if (t == 0){ red[r0*4 + wn] = mx0; red[r1*4 + wn] = mx1; }
    __syncthreads();
    float rm0 = fmaxf(fmaxf(red[r0*4+0], red[r0*4+1]), fmaxf(red[r0*4+2], red[r0*4+3]));
    float rm1 = fmaxf(fmaxf(red[r1*4+0], red[r1*4+1]), fmaxf(red[r1*4+2], red[r1*4+3]));
    __syncthreads();

    float s0 = 0.f, s1 = 0.f;
    #pragma unroll
    for (int c = 0; c < 4; c++)
        #pragma unroll
        for (int nt = 0; nt < 4; nt++){
            acc[c][nt][0] = __expf(acc[c][nt][0] - rm0);
            acc[c][nt][1] = __expf(acc[c][nt][1] - rm0);
            acc[c][nt][2] = __expf(acc[c][nt][2] - rm1);
            acc[c][nt][3] = __expf(acc[c][nt][3] - rm1);
            s0 += acc[c][nt][0] + acc[c][nt][1];
            s1 += acc[c][nt][2] + acc[c][nt][3];
        }
    #pragma unroll
    for (int o = 1; o <= 2; o <<= 1){
        s0 += __shfl_xor_sync(~0u, s0, o);
        s1 += __shfl_xor_sync(~0u, s1, o);
    }
    if (t == 0){ red[r0*4 + wn] = s0; red[r1*4 + wn] = s1; }
    __syncthreads();
    float inv0 = 1.f / (red[r0*4+0] + red[r0*4+1] + red[r0*4+2] + red[r0*4+3]);
    float inv1 = 1.f / (red[r1*4+0] + red[r1*4+1] + red[r1*4+2] + red[r1*4+3]);

    // AV: per 128-col chunk stage tf32(series) in smem, mma against V chunk
    float yacc[2][4];
    #pragma unroll
    for (int nt = 0; nt < 2; nt++)
        #pragma unroll
        for (int p = 0; p < 4; p++) yacc[nt][p] = 0.f;

    float* Srow0 = dsm + (A_BYTES + 2*B_BYTES)/4;
    float* p0 = Sb + (long)r0*512;
    float* p1 = Sb + (long)r1*512;

    #pragma unroll
    for (int c = 0; c < 4; c++){
        #pragma unroll
        for (int nt = 0; nt < 4; nt++){
            int colc = wn*32 + nt*8 + 2*t;
            float n00 = acc[c][nt][0]*inv0, n01 = acc[c][nt][1]*inv0;
            float n10 = acc[c][nt][2]*inv1, n11 = acc[c][nt][3]*inv1;
            Srow0[r0*SST + colc]   = tf32r(n00);
            Srow0[r0*SST + colc+1] = tf32r(n01);
            Srow0[r1*SST + colc]   = tf32r(n10);
            Srow0[r1*SST + colc+1] = tf32r(n11);
            *(float2*)&p0[c*128 + colc] = make_float2(n00, n01);
            *(float2*)&p1[c*128 + colc] = make_float2(n10, n11);
        }
        if (c < 3) { CPWAIT(1); } else { CPWAIT(0); }
        __syncthreads();

        const unsigned vb = sbB + (unsigned)(c & 1) * B_BYTES;
        #pragma unroll
        for (int kg = 0; kg < 8; kg++){
            uint4 a0 = ldmx4(sF + (unsigned)(kg*16 + 0)*4);
            uint4 a1 = ldmx4(sF + (unsigned)(kg*16 + 8)*4);
            #pragma unroll
            for (int nt = 0; nt < 2; nt++){
                uint4 bv = ldmx4(vb + vF + (unsigned)(nt*8*VST + kg*16)*4);
                mma8(yacc[nt], a0.x, a0.y, a0.z, a0.w, bv.x, bv.y);
                mma8(yacc[nt], a1.x, a1.y, a1.z, a1.w, bv.z, bv.w);
            }
        }
        __syncthreads();                   // protects sbS + V buffer (load-bearing)
        if (c + 2 < 4){ issueV(c + 2, c & 1); }
        CPCOMMIT();
    }

    // write y tile
    #pragma unroll
    for (int nt = 0; nt < 2; nt++){
        int col = wn*16 + nt*8 + 2*t;
        int rowA = m0 + r0, rowB = m0 + r1;
        *(float2*)&Yb[(long)rowA*512 + col] = make_float2(yacc[nt][0], yacc[nt][1]);
        *(float2*)&Yb[(long)rowB*512 + col] = make_float2(yacc[nt][2], yacc[nt][3]);
    }
}

// ---------------------------------------------------------------------------
// LN2 + scale/shift + silu (hs stored tf32-rounded)
// ---------------------------------------------------------------------------
__global__ void ln2_style_kernel(const float* __restrict__ g,
                                 const float* __restrict__ b)
{
    int row = blockIdx.x;
    int tid = threadIdx.x;
    int warp = tid >> 5, lane = tid & 31;
    int bb = row / TT;
    const float* yr = g_y + (size_t)row * DDIM;
    float x0 = yr[tid], x1 = yr[tid + 256];
    float s = x0 + x1, sq = x0*x0 + x1*x1;
    #pragma unroll
    for (int o = 16; o > 0; o >>= 1) {
        s  += __shfl_xor_sync(~0u, s,  o);
        sq += __shfl_xor_sync(~0u, sq, o);
    }
    __shared__ float sm[8], sm2[8];
    if (lane == 0) { sm[warp] = s; sm2[warp] = sq; }
    __syncthreads();
    float tot = 0.f, tot2 = 0.f;
    #pragma unroll
    for (int i = 0; i < 8; i++) { tot += sm[i]; tot2 += sm2[i]; }
    float mean = tot * (1.f / DDIM);
    float var  = tot2 * (1.f / DDIM) - mean * mean;
    float rstd = rsqrtf(var + 1e-5f);
    float n0 = (x0 - mean) * rstd * g[tid]       + b[tid];
    float n1 = (x1 - mean) * rstd * g[tid + 256] + b[tid + 256];
    const float* st = g_style + bb * (2*DDIM);
    float h0 = n0 * (1.f + st[tid])       + st[512 + tid];
    float h1 = n1 * (1.f + st[tid + 256]) + st[512 + tid + 256];
    g_hs[(size_t)row*DDIM + tid]       = tf32r(siluf(h0));
    g_hs[(size_t)row*DDIM + tid + 256] = tf32r(siluf(h1));
}

// ---------------------------------------------------------------------------
extern "C" void kernel_launch(void* const* d_in, const int* in_sizes, int n_in,
                              void* d_out, int out_size)
{
    const float* x    = (const float*)d_in[0];
    const float* emb  = (const float*)d_in[1];
    const float* Wq   = (const float*)d_in[2];
    const float* Wk   = (const float*)d_in[3];
    const float* Wv   = (const float*)d_in[4];
    const float* Wsig = (const float*)d_in[5];
    const float* ln1g = (const float*)d_in[6];
    const float* ln1b = (const float*)d_in[7];
    const float* embW = (const float*)d_in[8];
    const float* embB = (const float*)d_in[9];
    const float* ln2g = (const float*)d_in[10];
    const float* ln2b = (const float*)d_in[11];
    const float* outW = (const float*)d_in[12];
    const float* outB = (const float*)d_in[13];

    float* out    = (float*)d_out;
    float* outY   = out;
    float* outS   = out + YN;
    float* outP   = outS + SN;
    float* outSig = outP + SN;

    float *pxn, *pq, *pk, *pv, *py, *phs, *pwr;
    cudaGetSymbolAddress((void**)&pxn, g_xn);
    cudaGetSymbolAddress((void**)&pq,  g_q);
    cudaGetSymbolAddress((void**)&pk,  g_k);
    cudaGetSymbolAddress((void**)&pv,  g_v);
    cudaGetSymbolAddress((void**)&py,  g_y);
    cudaGetSymbolAddress((void**)&phs, g_hs);
    cudaGetSymbolAddress((void**)&pwr, g_wr);

    const int SMG = 3*2*128*36*4;                            // 110592
    const int SMF = 8704 + 2*34816 + 32*132*4 + 512;         // 95744

    cudaFuncSetAttribute(tf32_gemm2<true >, cudaFuncAttributeMaxDynamicSharedMemorySize, SMG);
    cudaFuncSetAttribute(tf32_gemm2<false>, cudaFuncAttributeMaxDynamicSharedMemorySize, SMG);
    cudaFuncSetAttribute(mega_attn_kernel,  cudaFuncAttributeMaxDynamicSharedMemorySize, SMF);

    // 1) LN1 + sigma + weight pre-round (packed)
    ln1_sigma_roundw_kernel<<<MROWS + WSZ/256, 256>>>(
        x, ln1g, ln1b, Wsig, Wq, Wk, Wv, outW);

    // 2) merged QKV projection (one launch, per-block routing)
    tf32_gemm2<true><<<dim3(12, MROWS/128), 256, SMG>>>(
        pxn, pwr, pq, pk, pv, nullptr, nullptr);

    // 3) MEGA: attention (scores+softmax+AV) + prior + sigma_full + style
    mega_attn_kernel<<<8192 + 128, 256, SMF>>>(
        pq, pk, pv, outS, py, outP, outSig, emb, embW, embB);

    // 4) LN2 + style + silu
    ln2_style_kernel<<<MROWS, 256>>>(ln2g, ln2b);

    // 5) y_out = x + silu_h @ out_W^T + out_b
    tf32_gemm2<false><<<dim3(4, MROWS/128), 256, SMG>>>(
        phs, pwr + 3*WSZ, outY, nullptr, nullptr, outB, x);
}

// round 11
// speedup vs baseline: 1.0972x; 1.0379x over previous
#include <cuda_runtime.h>
#include <cuda_bf16.h>

// Problem constants
#define BQ   32
#define TT   512
#define DDIM 512
#define HH   8
#define HD   64
#define TEDIM 2048
#define MROWS (BQ*TT)            // 16384
#define YN ((size_t)BQ*TT*DDIM)  // 8388608
#define SN ((size_t)BQ*HH*TT*TT) // 67108864
#define WSZ (DDIM*DDIM)          // 262144

// Scratch (device globals — no allocation allowed)
__device__ float g_xn[BQ*TT*DDIM];
__device__ __nv_bfloat16 g_qh[BQ*TT*DDIM];   // Q in bf16
__device__ __nv_bfloat16 g_kh[BQ*TT*DDIM];   // K in bf16
__device__ float g_v [BQ*TT*DDIM];   // stored TRANSPOSED: [b][h*64+d][t] (tf32)
__device__ float g_y [BQ*TT*DDIM];
__device__ float g_hs[BQ*TT*DDIM];
__device__ float g_sigma[BQ*HH*TT];
__device__ float g_style[BQ*2*DDIM];
__device__ float g_wr[4*WSZ];        // tf32-rounded [Wq;Wk;Wv] (1536x512) + outW

__device__ __forceinline__ float siluf(float z){ return z / (1.f + expf(-z)); }

__device__ __forceinline__ float tf32r(float f){
    unsigned u; asm("cvt.rna.tf32.f32 %0, %1;" : "=r"(u) : "f"(f));
    return __uint_as_float(u);
}

__device__ __forceinline__ void mma8(float* c,
    unsigned a0, unsigned a1, unsigned a2, unsigned a3,
    unsigned b0, unsigned b1)
{
    asm volatile(
        "mma.sync.aligned.m16n8k8.row.col.f32.tf32.tf32.f32 "
        "{%0,%1,%2,%3}, {%4,%5,%6,%7}, {%8,%9}, {%0,%1,%2,%3};"
        : "+f"(c[0]), "+f"(c[1]), "+f"(c[2]), "+f"(c[3])
        : "r"(a0), "r"(a1), "r"(a2), "r"(a3), "r"(b0), "r"(b1));
}

__device__ __forceinline__ void mma16bf(float* c,
    unsigned a0, unsigned a1, unsigned a2, unsigned a3,
    unsigned b0, unsigned b1)
{
    asm volatile(
        "mma.sync.aligned.m16n8k16.row.col.f32.bf16.bf16.f32 "
        "{%0,%1,%2,%3}, {%4,%5,%6,%7}, {%8,%9}, {%0,%1,%2,%3};"
        : "+f"(c[0]), "+f"(c[1]), "+f"(c[2]), "+f"(c[3])
        : "r"(a0), "r"(a1), "r"(a2), "r"(a3), "r"(b0), "r"(b1));
}

__device__ __forceinline__ void cp16(unsigned dst, const void* src){
    asm volatile("cp.async.cg.shared.global [%0], [%1], 16;" :: "r"(dst), "l"(src));
}
#define CPCOMMIT() asm volatile("cp.async.commit_group;" ::: "memory")
#define CPWAIT(n)  asm volatile("cp.async.wait_group %0;" :: "n"(n) : "memory")

__device__ __forceinline__ uint4 ldmx4(unsigned a){
    uint4 r;
    asm volatile("ldmatrix.sync.aligned.m8n8.x4.shared.b16 {%0,%1,%2,%3}, [%4];"
        : "=r"(r.x), "=r"(r.y), "=r"(r.z), "=r"(r.w) : "r"(a));
    return r;
}

// ---------------------------------------------------------------------------
// LN1 + sigma, with round_w blocks packed into the same launch.
// ---------------------------------------------------------------------------
__global__ void ln1_sigma_roundw_kernel(const float* __restrict__ x,
                                        const float* __restrict__ g,
                                        const float* __restrict__ b,
                                        const float* __restrict__ Wsig,
                                        const float* __restrict__ w0,
                                        const float* __restrict__ w1,
                                        const float* __restrict__ w2,
                                        const float* __restrict__ w3)
{
    int tid = threadIdx.x;
    if (blockIdx.x >= MROWS){
        int i = (blockIdx.x - MROWS) * 256 + tid;
        g_wr[i]         = tf32r(w0[i]);
        g_wr[i +   WSZ] = tf32r(w1[i]);
        g_wr[i + 2*WSZ] = tf32r(w2[i]);
        g_wr[i + 3*WSZ] = tf32r(w3[i]);
        return;
    }
    int row = blockIdx.x;
    int warp = tid >> 5, lane = tid & 31;
    const float* xr = x + (size_t)row * DDIM;
    float x0 = xr[tid], x1 = xr[tid + 256];
    float s = x0 + x1, sq = x0*x0 + x1*x1;
    #pragma unroll
    for (int o = 16; o > 0; o >>= 1) {
        s  += __shfl_xor_sync(~0u, s,  o);
        sq += __shfl_xor_sync(~0u, sq, o);
    }
    __shared__ float sm[8], sm2[8];
    if (lane == 0) { sm[warp] = s; sm2[warp] = sq; }
    __syncthreads();
    float tot = 0.f, tot2 = 0.f;
    #pragma unroll
    for (int i = 0; i < 8; i++) { tot += sm[i]; tot2 += sm2[i]; }
    float mean = tot * (1.f / DDIM);
    float var  = tot2 * (1.f / DDIM) - mean * mean;
    float rstd = rsqrtf(var + 1e-5f);
    g_xn[(size_t)row*DDIM + tid]       = tf32r((x0 - mean) * rstd * g[tid]       + b[tid]);
    g_xn[(size_t)row*DDIM + tid + 256] = tf32r((x1 - mean) * rstd * g[tid + 256] + b[tid + 256]);

    float acc[HH];
    #pragma unroll
    for (int h = 0; h < HH; h++)
        acc[h] = x0 * Wsig[tid*HH + h] + x1 * Wsig[(tid+256)*HH + h];
    #pragma unroll
    for (int h = 0; h < HH; h++)
        #pragma unroll
        for (int o = 16; o > 0; o >>= 1)
            acc[h] += __shfl_xor_sync(~0u, acc[h], o);
    __shared__ float red[8][HH];
    if (lane == 0)
        #pragma unroll
        for (int h = 0; h < HH; h++) red[warp][h] = acc[h];
    __syncthreads();
    if (tid < HH) {
        float z = 0.f;
        #pragma unroll
        for (int w = 0; w < 8; w++) z += red[w][tid];
        float sg  = 1.f / (1.f + expf(-5.f * z)) + 1e-5f;
        float sig = exp2f(sg * 1.5849625007211562f) - 1.f;   // 3^sg - 1
        int bb = row / TT, t = row % TT;
        g_sigma[(bb*HH + tid)*TT + t] = sig;
    }
}

// ---------------------------------------------------------------------------
// tf32 NT GEMM v2 (BK=32, 3-stage cp.async).
// QKV=true: merged [1536,512] weights; Q/K stored bf16, V tf32 transposed.
// QKV=false: out-proj, C = A@B^T + bias + res (fp32).
// ---------------------------------------------------------------------------
template<bool QKV>
__global__ void __launch_bounds__(256,2)
tf32_gemm2(const float* __restrict__ A, const float* __restrict__ Bw,
           float* __restrict__ Cq, float* __restrict__ Ck, float* __restrict__ Cv,
           const float* __restrict__ bias, const float* __restrict__ res)
{
    constexpr int ST  = 36;                // 32 + 4 pad (floats)
    constexpr int STG = 128*ST*4;          // per-operand stage bytes

    extern __shared__ float dsm[];
    const unsigned sb = (unsigned)__cvta_generic_to_shared(dsm);
    const unsigned aS = sb;
    const unsigned bS = sb + 3*STG;

    const int tid  = threadIdx.x;
    const int lane = tid & 31;
    const int wid  = tid >> 5;
    const int wm   = wid & 1;
    const int wn   = wid >> 1;
    const int g    = lane >> 2;
    const int t    = lane & 3;

    const int m0 = blockIdx.y * 128;
    const int n0 = blockIdx.x * 128;

    const int rl = tid >> 3;               // 0..31
    const int qc = tid & 7;                // 16B chunk in BK32

    const float* Ag = A  + (long)(m0 + rl) * 512 + qc*4;
    const float* Bg = Bw + (long)(n0 + rl) * 512 + qc*4;
    const unsigned dA = (unsigned)(rl*ST + qc*4) * 4;

    auto issue = [&](int st, int k0){
        unsigned ab = aS + st*STG, bb = bS + st*STG;
        #pragma unroll
        for (int e = 0; e < 4; e++){
            cp16(ab + dA + e*32*ST*4, Ag + (long)e*32*512 + k0);
            cp16(bb + dA + e*32*ST*4, Bg + (long)e*32*512 + k0);
        }
    };

    const int arow = (lane & 7) + ((lane >> 3) & 1) * 8;
    const int acol = (lane >> 4) * 4;
    const unsigned aFB = (unsigned)((wm*64 + arow)*ST + acol) * 4;
    const unsigned bFB = (unsigned)((wn*32 + (lane & 7))*ST + (lane >> 3)*4) * 4;

    float acc[4][4][4];
    #pragma unroll
    for (int i = 0; i < 4; i++)
        #pragma unroll
        for (int j = 0; j < 4; j++)
            #pragma unroll
            for (int p = 0; p < 4; p++) acc[i][j][p] = 0.f;

    issue(0, 0);  CPCOMMIT();
    issue(1, 32); CPCOMMIT();

    int buf = 0;
    for (int k0 = 0; k0 < 512; k0 += 32) {
        CPWAIT(1);
        __syncthreads();
        if (k0 + 64 < 512) {
            int nb = buf + 2; if (nb >= 3) nb -= 3;
            issue(nb, k0 + 64);
        }
        CPCOMMIT();

        const unsigned ab = aS + buf*STG;
        const unsigned bb = bS + buf*STG;

        uint4 bfr[4][2];
        #pragma unroll
        for (int nt = 0; nt < 4; nt++)
            #pragma unroll
            for (int kg = 0; kg < 2; kg++)
                bfr[nt][kg] = ldmx4(bb + bFB + (unsigned)(nt*8*ST + kg*16)*4);

        #pragma unroll
        for (int ks = 0; ks < 4; ks++) {
            #pragma unroll
            for (int mt = 0; mt < 4; mt++) {
                uint4 a = ldmx4(ab + aFB + (unsigned)(mt*16*ST + ks*8)*4);
                #pragma unroll
                for (int nt = 0; nt < 4; nt++)
                    mma8(acc[mt][nt], a.x, a.y, a.z, a.w,
                         (ks & 1) ? bfr[nt][ks>>1].z : bfr[nt][ks>>1].x,
                         (ks & 1) ? bfr[nt][ks>>1].w : bfr[nt][ks>>1].y);
            }
        }
        buf++; if (buf == 3) buf = 0;
    }

    // Epilogue
    #pragma unroll
    for (int mt = 0; mt < 4; mt++){
        #pragma unroll
        for (int nt = 0; nt < 4; nt++){
            int row = m0 + wm*64 + mt*16 + g;
            int col = n0 + wn*32 + nt*8 + 2*t;
            float v0 = acc[mt][nt][0], v1 = acc[mt][nt][1];
            float v2 = acc[mt][nt][2], v3 = acc[mt][nt][3];
            if (QKV){
                if (n0 < 512){
                    __nv_bfloat16* qh = (__nv_bfloat16*)Cq;
                    __nv_bfloat162 h0, h1;
                    h0.x = __float2bfloat16(v0); h0.y = __float2bfloat16(v1);
                    h1.x = __float2bfloat16(v2); h1.y = __float2bfloat16(v3);
                    *(__nv_bfloat162*)&qh[(long)row*512 + col]     = h0;
                    *(__nv_bfloat162*)&qh[(long)(row+8)*512 + col] = h1;
                } else if (n0 < 1024){
                    int c2 = col - 512;
                    __nv_bfloat16* kh = (__nv_bfloat16*)Ck;
                    __nv_bfloat162 h0, h1;
                    h0.x = __float2bfloat16(v0); h0.y = __float2bfloat16(v1);
                    h1.x = __float2bfloat16(v2); h1.y = __float2bfloat16(v3);
                    *(__nv_bfloat162*)&kh[(long)row*512 + c2]     = h0;
                    *(__nv_bfloat162*)&kh[(long)(row+8)*512 + c2] = h1;
                } else {
                    int vc = col - 1024;
                    long base0 = (long)(row >> 9) * (512L*512) + (row & 511);
                    Cv[base0 + (long)vc*512]         = tf32r(v0);
                    Cv[base0 + (long)(vc+1)*512]     = tf32r(v1);
                    Cv[base0 + 8 + (long)vc*512]     = tf32r(v2);
                    Cv[base0 + 8 + (long)(vc+1)*512] = tf32r(v3);
                }
            } else {
                v0 += bias[col];   v1 += bias[col+1];
                v2 += bias[col];   v3 += bias[col+1];
                v0 += res[(long)row*512 + col];
                v1 += res[(long)row*512 + col+1];
                v2 += res[(long)(row+8)*512 + col];
                v3 += res[(long)(row+8)*512 + col+1];
                *(float2*)&Cq[(long)row*512 + col]     = make_float2(v0, v1);
                *(float2*)&Cq[(long)(row+8)*512 + col] = make_float2(v2, v3);
            }
        }
    }
}

// ---------------------------------------------------------------------------
// MEGA kernel: attention (bf16 QK + tf32 AV) + prior + style.
// Same smem map as proven round-10 version; bf16 K underfills B buffers.
// ---------------------------------------------------------------------------
__global__ void __launch_bounds__(256,2)
mega_attn_kernel(const __nv_bfloat16* __restrict__ Q,
                 const __nv_bfloat16* __restrict__ Kt,
                 const float* __restrict__ Vt,
                 float* __restrict__ S, float* __restrict__ Y,
                 float* __restrict__ prior, float* __restrict__ sfull,
                 const float* __restrict__ emb,
                 const float* __restrict__ embW,
                 const float* __restrict__ embB)
{
    extern __shared__ float dsm[];
    const int tid  = threadIdx.x;
    const unsigned bx = blockIdx.x;

    // ---------------- style blocks ----------------
    if (bx >= 8192){
        int sb = bx - 8192;
        int bb = sb >> 2, part = sb & 3;
        float* se = dsm;
        for (int i = tid; i < TEDIM; i += 256){
            float e = emb[(size_t)bb * TEDIM + i];
            se[i] = siluf(e);
        }
        __syncthreads();
        int j = part*256 + tid;
        float acc = 0.f;
        for (int k = 0; k < TEDIM; k++)
            acc += se[k] * embW[(size_t)k * (2*DDIM) + j];
        g_style[bb * (2*DDIM) + j] = acc + embB[j];
        return;
    }

    // ---------------- prior blocks ----------------
    if (bx & 1){
        long base = (long)(bx >> 1) * 32;
        int w = tid >> 5, l = tid & 31;
        #pragma unroll
        for (int i = 0; i < 4; i++){
            long row = base + w*4 + i;
            int n = (int)(row & 511);
            float s = g_sigma[row];
            float inv2 = -1.f / (2.f * s * s);
            float coef = 0.3989422804014327f / s;
            float4 sv = make_float4(s, s, s, s);
            float4* pp = (float4*)(prior + row * TT);
            float4* sp = (float4*)(sfull + row * TT);
            #pragma unroll
            for (int j = 0; j < 4; j++){
                int c4 = l + j*32;
                int m = c4 * 4;
                float d0 = (float)(n - m);
                float d1 = (float)(n - (m+1));
                float d2 = (float)(n - (m+2));
                float d3 = (float)(n - (m+3));
                float4 pv;
                pv.x = __expf(d0*d0*inv2) * coef;
                pv.y = __expf(d1*d1*inv2) * coef;
                pv.z = __expf(d2*d2*inv2) * coef;
                pv.w = __expf(d3*d3*inv2) * coef;
                pp[c4] = pv;
                sp[c4] = sv;
            }
        }
        return;
    }

    // ---------------- attention blocks ----------------
    const int idx = bx >> 1;
    const int bh = idx >> 4;          // b*8+h
    const int m0 = (idx & 15) * 32;

    constexpr int VST = 132;          // V row stride (floats)
    constexpr int SST = 132;          // series staging stride (floats)
    constexpr int HROW = 144;         // bf16 tile row stride (bytes) = 72 bf16
    const unsigned A_BYTES = 8704;    // Q region (bf16 uses 32*144=4608 of it)
    const unsigned B_BYTES = 34816;   // K/V buffers (bf16 K uses 128*144=18432)

    const unsigned sb  = (unsigned)__cvta_generic_to_shared(dsm);
    const unsigned sbA = sb;
    const unsigned sbB = sb + A_BYTES;
    const unsigned sbS = sb + A_BYTES + 2*B_BYTES;       // series chunk 32x132
    float* red = dsm + (A_BYTES + 2*B_BYTES)/4 + 32*SST; // [32][4]

    const int lane = tid & 31;
    const int wid  = tid >> 5;
    const int wm   = wid & 1;
    const int wn   = wid >> 1;        // 0..3
    const int g    = lane >> 2;
    const int t    = lane & 3;

    const int b  = bh >> 3, h = bh & 7;

    const __nv_bfloat16* Qb = Q + ((long)b*512 + m0)*512 + h*64;
    const __nv_bfloat16* Kb = Kt + ((long)b*512)*512 + h*64;
    const float* Vb = Vt + (long)b*(512L*512) + (long)h*64*512; // [64 d][512 t]
    float* Sb = S + ((long)bh*512 + m0)*512;
    float* Yb = Y + ((long)b*512)*512 + h*64;

    // bf16 fragment offsets (bytes)
    const int arow = (lane & 7) + ((lane >> 3) & 1) * 8;
    const unsigned aFh = sbA + (unsigned)((wm*16 + arow)*HROW + (lane >> 4)*16);
    const unsigned bFh0 = (unsigned)((wn*32 + (lane & 7) + ((lane >> 4) & 1)*8)*HROW
                                     + ((lane >> 3) & 1)*16);
    const unsigned bFh1 = bFh0 + (unsigned)(16*HROW);

    // tf32 AV fragment offsets (unchanged from proven version)
    const unsigned sF  = sbS + (unsigned)((wm*16 + arow)*SST + (lane >> 4)*4) * 4;
    const unsigned vF  = (unsigned)((wn*16 + (lane & 7))*VST + (lane >> 3)*4) * 4;

    auto issueB = [&](int chunk, int bufb){
        unsigned dst = sbB + (unsigned)bufb * B_BYTES;
        const __nv_bfloat16* src = Kb + (long)(chunk*128)*512;
        #pragma unroll
        for (int e = 0; e < 4; e++){
            int idx2 = tid + 256*e;           // 0..1023
            int r = idx2 >> 3, c8 = idx2 & 7; // 128 rows x 8 16B-units
            cp16(dst + (unsigned)(r*HROW + c8*16), src + (long)r*512 + c8*8);
        }
    };
    auto issueV = [&](int chunk, int bufb){
        unsigned dst = sbB + (unsigned)bufb * B_BYTES;
        #pragma unroll
        for (int e = 0; e < 8; e++){
            int idx2 = tid + 256*e;       // 0..2047
            int r  = idx2 >> 5;           // 0..63  (d-row)
            int qc = idx2 & 31;           // 0..31  (16B chunk of 128 t-cols)
            cp16(dst + (unsigned)(r*VST + qc*4)*4,
                 Vb + (long)r*512 + chunk*128 + qc*4);
        }
    };

    // group 0: Q tile (bf16) + K chunk 0
    {
        int r = tid >> 3, c8 = tid & 7;   // 32 rows x 8 units = 256 cp16
        cp16(sbA + (unsigned)(r*HROW + c8*16), Qb + (long)r*512 + c8*8);
        issueB(0, 0);
        CPCOMMIT();
    }

    float acc[4][4][4];
    #pragma unroll
    for (int c = 0; c < 4; c++)
        #pragma unroll
        for (int nt = 0; nt < 4; nt++)
            #pragma unroll
            for (int p = 0; p < 4; p++) acc[c][nt][p] = 0.f;

    for (int c = 0; c < 4; c++){
        CPWAIT(0);
        __syncthreads();                  // orders prior-iter mma before refill
        if (c + 1 < 4) issueB(c + 1, (c + 1) & 1);
        CPCOMMIT();

        const unsigned bb2 = sbB + (unsigned)(c & 1) * B_BYTES;
        #pragma unroll
        for (int ks = 0; ks < 4; ks++){   // 4 k16 steps cover 64 dims
            uint4 a = ldmx4(aFh + (unsigned)(ks*32));
            uint4 bv0 = ldmx4(bb2 + bFh0 + (unsigned)(ks*32));
            mma16bf(acc[c][0], a.x, a.y, a.z, a.w, bv0.x, bv0.y);
            mma16bf(acc[c][1], a.x, a.y, a.z, a.w, bv0.z, bv0.w);
            uint4 bv1 = ldmx4(bb2 + bFh1 + (unsigned)(ks*32));
            mma16bf(acc[c][2], a.x, a.y, a.z, a.w, bv1.x, bv1.y);
            mma16bf(acc[c][3], a.x, a.y, a.z, a.w, bv1.z, bv1.w);
        }
    }
    __syncthreads();                      // protect V prefetch overwriting buf 1

    // prefetch V chunks 0,1 into the two (now free) B buffers
    issueV(0, 0); CPCOMMIT();
    issueV(1, 1); CPCOMMIT();

    // softmax: scale, max, exp, sum (overlaps V prefetch)
    #pragma unroll
    for (int c = 0; c < 4; c++)
        #pragma unroll
        for (int nt = 0; nt < 4; nt++)
            #pragma unroll
            for (int p = 0; p < 4; p++) acc[c][nt][p] *= (1.f/64.f);

    const int r0 = wm*16 + g, r1 = r0 + 8;

    float mx0 = -1e30f, mx1 = -1e30f;
    #pragma unroll
    for (int c = 0; c < 4; c++)
        #pragma unroll
        for (int nt = 0; nt < 4; nt++){
            mx0 = fmaxf(mx0, fmaxf(acc[c][nt][0], acc[c][nt][1]));
            mx1 = fmaxf(mx1, fmaxf(acc[c][nt][2], acc[c][nt][3]));
        }
    #pragma unroll
    for (int o = 1; o <= 2; o <<= 1){
        mx0 = fmaxf(mx0, __shfl_xor_sync(~0u, mx0, o));
        mx1 = fmaxf(mx1, __shfl_xor_sync(~0u, mx1, o));
    }
    if (t == 0){ red[r0*4 + wn] = mx0; red[r1*4 + wn] = mx1; }
    __syncthreads();
    float rm0 = fmaxf(fmaxf(red[r0*4+0], red[r0*4+1]), fmaxf(red[r0*4+2], red[r0*4+3]));
    float rm1 = fmaxf(fmaxf(red[r1*4+0], red[r1*4+1]), fmaxf(red[r1*4+2], red[r1*4+3]));
    __syncthreads();

    float s0 = 0.f, s1 = 0.f;
    #pragma unroll
    for (int c = 0; c < 4; c++)
        #pragma unroll
        for (int nt = 0; nt < 4; nt++){
            acc[c][nt][0] = __expf(acc[c][nt][0] - rm0);
            acc[c][nt][1] = __expf(acc[c][nt][1] - rm0);
            acc[c][nt][2] = __expf(acc[c][nt][2] - rm1);
            acc[c][nt][3] = __expf(acc[c][nt][3] - rm1);
            s0 += acc[c][nt][0] + acc[c][nt][1];
            s1 += acc[c][nt][2] + acc[c][nt][3];
        }
    #pragma unroll
    for (int o = 1; o <= 2; o <<= 1){
        s0 += __shfl_xor_sync(~0u, s0, o);
        s1 += __shfl_xor_sync(~0u, s1, o);
    }
    if (t == 0){ red[r0*4 + wn] = s0; red[r1*4 + wn] = s1; }
    __syncthreads();
    float inv0 = 1.f / (red[r0*4+0] + red[r0*4+1] + red[r0*4+2] + red[r0*4+3]);
    float inv1 = 1.f / (red[r1*4+0] + red[r1*4+1] + red[r1*4+2] + red[r1*4+3]);

    // AV: per 128-col chunk stage tf32(series) in smem, mma against V chunk
    float yacc[2][4];
    #pragma unroll
    for (int nt = 0; nt < 2; nt++)
        #pragma unroll
        for (int p = 0; p < 4; p++) yacc[nt][p] = 0.f;

    float* Srow0 = dsm + (A_BYTES + 2*B_BYTES)/4;
    float* p0 = Sb + (long)r0*512;
    float* p1 = Sb + (long)r1*512;

    #pragma unroll
    for (int c = 0; c < 4; c++){
        #pragma unroll
        for (int nt = 0; nt < 4; nt++){
            int colc = wn*32 + nt*8 + 2*t;
            float n00 = acc[c][nt][0]*inv0, n01 = acc[c][nt][1]*inv0;
            float n10 = acc[c][nt][2]*inv1, n11 = acc[c][nt][3]*inv1;
            Srow0[r0*SST + colc]   = tf32r(n00);
            Srow0[r0*SST + colc+1] = tf32r(n01);
            Srow0[r1*SST + colc]   = tf32r(n10);
            Srow0[r1*SST + colc+1] = tf32r(n11);
            *(float2*)&p0[c*128 + colc] = make_float2(n00, n01);
            *(float2*)&p1[c*128 + colc] = make_float2(n10, n11);
        }
        if (c < 3) { CPWAIT(1); } else { CPWAIT(0); }
        __syncthreads();

        const unsigned vb = sbB + (unsigned)(c & 1) * B_BYTES;
        #pragma unroll
        for (int kg = 0; kg < 8; kg++){
            uint4 a0 = ldmx4(sF + (unsigned)(kg*16 + 0)*4);
            uint4 a1 = ldmx4(sF + (unsigned)(kg*16 + 8)*4);
            #pragma unroll
            for (int nt = 0; nt < 2; nt++){
                uint4 bv = ldmx4(vb + vF + (unsigned)(nt*8*VST + kg*16)*4);
                mma8(yacc[nt], a0.x, a0.y, a0.z, a0.w, bv.x, bv.y);
                mma8(yacc[nt], a1.x, a1.y, a1.z, a1.w, bv.z, bv.w);
            }
        }
        __syncthreads();                   // protects sbS + V buffer (load-bearing)
        if (c + 2 < 4){ issueV(c + 2, c & 1); }
        CPCOMMIT();
    }

    // write y tile
    #pragma unroll
    for (int nt = 0; nt < 2; nt++){
        int col = wn*16 + nt*8 + 2*t;
        int rowA = m0 + r0, rowB = m0 + r1;
        *(float2*)&Yb[(long)rowA*512 + col] = make_float2(yacc[nt][0], yacc[nt][1]);
        *(float2*)&Yb[(long)rowB*512 + col] = make_float2(yacc[nt][2], yacc[nt][3]);
    }
}

// ---------------------------------------------------------------------------
// LN2 + scale/shift + silu (hs stored tf32-rounded)
// ---------------------------------------------------------------------------
__global__ void ln2_style_kernel(const float* __restrict__ g,
                                 const float* __restrict__ b)
{
    int row = blockIdx.x;
    int tid = threadIdx.x;
    int warp = tid >> 5, lane = tid & 31;
    int bb = row / TT;
    const float* yr = g_y + (size_t)row * DDIM;
    float x0 = yr[tid], x1 = yr[tid + 256];
    float s = x0 + x1, sq = x0*x0 + x1*x1;
    #pragma unroll
    for (int o = 16; o > 0; o >>= 1) {
        s  += __shfl_xor_sync(~0u, s,  o);
        sq += __shfl_xor_sync(~0u, sq, o);
    }
    __shared__ float sm[8], sm2[8];
    if (lane == 0) { sm[warp] = s; sm2[warp] = sq; }
    __syncthreads();
    float tot = 0.f, tot2 = 0.f;
    #pragma unroll
    for (int i = 0; i < 8; i++) { tot += sm[i]; tot2 += sm2[i]; }
    float mean = tot * (1.f / DDIM);
    float var  = tot2 * (1.f / DDIM) - mean * mean;
    float rstd = rsqrtf(var + 1e-5f);
    float n0 = (x0 - mean) * rstd * g[tid]       + b[tid];
    float n1 = (x1 - mean) * rstd * g[tid + 256] + b[tid + 256];
    const float* st = g_style + bb * (2*DDIM);
    float h0 = n0 * (1.f + st[tid])       + st[512 + tid];
    float h1 = n1 * (1.f + st[tid + 256]) + st[512 + tid + 256];
    g_hs[(size_t)row*DDIM + tid]       = tf32r(siluf(h0));
    g_hs[(size_t)row*DDIM + tid + 256] = tf32r(siluf(h1));
}

// ---------------------------------------------------------------------------
extern "C" void kernel_launch(void* const* d_in, const int* in_sizes, int n_in,
                              void* d_out, int out_size)
{
    const float* x    = (const float*)d_in[0];
    const float* emb  = (const float*)d_in[1];
    const float* Wq   = (const float*)d_in[2];
    const float* Wk   = (const float*)d_in[3];
    const float* Wv   = (const float*)d_in[4];
    const float* Wsig = (const float*)d_in[5];
    const float* ln1g = (const float*)d_in[6];
    const float* ln1b = (const float*)d_in[7];
    const float* embW = (const float*)d_in[8];
    const float* embB = (const float*)d_in[9];
    const float* ln2g = (const float*)d_in[10];
    const float* ln2b = (const float*)d_in[11];
    const float* outW = (const float*)d_in[12];
    const float* outB = (const float*)d_in[13];

    float* out    = (float*)d_out;
    float* outY   = out;
    float* outS   = out + YN;
    float* outP   = outS + SN;
    float* outSig = outP + SN;

    float *pxn, *pv, *py, *phs, *pwr;
    __nv_bfloat16 *pqh, *pkh;
    cudaGetSymbolAddress((void**)&pxn, g_xn);
    cudaGetSymbolAddress((void**)&pqh, g_qh);
    cudaGetSymbolAddress((void**)&pkh, g_kh);
    cudaGetSymbolAddress((void**)&pv,  g_v);
    cudaGetSymbolAddress((void**)&py,  g_y);
    cudaGetSymbolAddress((void**)&phs, g_hs);
    cudaGetSymbolAddress((void**)&pwr, g_wr);

    const int SMG = 3*2*128*36*4;                            // 110592
    const int SMF = 8704 + 2*34816 + 32*132*4 + 512;         // 95744

    cudaFuncSetAttribute(tf32_gemm2<true >, cudaFuncAttributeMaxDynamicSharedMemorySize, SMG);
    cudaFuncSetAttribute(tf32_gemm2<false>, cudaFuncAttributeMaxDynamicSharedMemorySize, SMG);
    cudaFuncSetAttribute(mega_attn_kernel,  cudaFuncAttributeMaxDynamicSharedMemorySize, SMF);

    // 1) LN1 + sigma + weight pre-round (packed)
    ln1_sigma_roundw_kernel<<<MROWS + WSZ/256, 256>>>(
        x, ln1g, ln1b, Wsig, Wq, Wk, Wv, outW);

    // 2) merged QKV projection (Q/K -> bf16, V -> tf32 transposed)
    tf32_gemm2<true><<<dim3(12, MROWS/128), 256, SMG>>>(
        pxn, pwr, (float*)pqh, (float*)pkh, pv, nullptr, nullptr);

    // 3) MEGA: attention (bf16 QK + tf32 AV) + prior + sigma_full + style
    mega_attn_kernel<<<8192 + 128, 256, SMF>>>(
        pqh, pkh, pv, outS, py, outP, outSig, emb, embW, embB);

    // 4) LN2 + style + silu
    ln2_style_kernel<<<MROWS, 256>>>(ln2g, ln2b);

    // 5) y_out = x + silu_h @ out_W^T + out_b
    tf32_gemm2<false><<<dim3(4, MROWS/128), 256, SMG>>>(
        phs, pwr + 3*WSZ, outY, nullptr, nullptr, outB, x);
}

// round 12
// speedup vs baseline: 1.2343x; 1.1250x over previous
#include <cuda_runtime.h>
#include <cuda_bf16.h>

// Problem constants
#define BQ   32
#define TT   512
#define DDIM 512
#define HH   8
#define HD   64
#define TEDIM 2048
#define MROWS (BQ*TT)            // 16384
#define YN ((size_t)BQ*TT*DDIM)  // 8388608
#define SN ((size_t)BQ*HH*TT*TT) // 67108864
#define WSZ (DDIM*DDIM)          // 262144

// Scratch (device globals — no allocation allowed)
__device__ __nv_bfloat16 g_xnh[BQ*TT*DDIM];  // LN1 output, bf16
__device__ __nv_bfloat16 g_qh[BQ*TT*DDIM];   // Q in bf16
__device__ __nv_bfloat16 g_kh[BQ*TT*DDIM];   // K in bf16
__device__ float g_v [BQ*TT*DDIM];   // stored TRANSPOSED: [b][h*64+d][t] (tf32)
__device__ float g_y [BQ*TT*DDIM];
__device__ float g_hs[BQ*TT*DDIM];
__device__ float g_sigma[BQ*HH*TT];
__device__ float g_style[BQ*2*DDIM];
__device__ __nv_bfloat16 g_wh[3*WSZ];        // bf16 [Wq;Wk;Wv] (1536x512)
__device__ float g_wr[WSZ];                  // tf32-rounded outW

__device__ __forceinline__ float siluf(float z){ return z / (1.f + expf(-z)); }

__device__ __forceinline__ float tf32r(float f){
    unsigned u; asm("cvt.rna.tf32.f32 %0, %1;" : "=r"(u) : "f"(f));
    return __uint_as_float(u);
}

__device__ __forceinline__ void mma8(float* c,
    unsigned a0, unsigned a1, unsigned a2, unsigned a3,
    unsigned b0, unsigned b1)
{
    asm volatile(
        "mma.sync.aligned.m16n8k8.row.col.f32.tf32.tf32.f32 "
        "{%0,%1,%2,%3}, {%4,%5,%6,%7}, {%8,%9}, {%0,%1,%2,%3};"
        : "+f"(c[0]), "+f"(c[1]), "+f"(c[2]), "+f"(c[3])
        : "r"(a0), "r"(a1), "r"(a2), "r"(a3), "r"(b0), "r"(b1));
}

__device__ __forceinline__ void mma16bf(float* c,
    unsigned a0, unsigned a1, unsigned a2, unsigned a3,
    unsigned b0, unsigned b1)
{
    asm volatile(
        "mma.sync.aligned.m16n8k16.row.col.f32.bf16.bf16.f32 "
        "{%0,%1,%2,%3}, {%4,%5,%6,%7}, {%8,%9}, {%0,%1,%2,%3};"
        : "+f"(c[0]), "+f"(c[1]), "+f"(c[2]), "+f"(c[3])
        : "r"(a0), "r"(a1), "r"(a2), "r"(a3), "r"(b0), "r"(b1));
}

__device__ __forceinline__ void cp16(unsigned dst, const void* src){
    asm volatile("cp.async.cg.shared.global [%0], [%1], 16;" :: "r"(dst), "l"(src));
}
#define CPCOMMIT() asm volatile("cp.async.commit_group;" ::: "memory")
#define CPWAIT(n)  asm volatile("cp.async.wait_group %0;" :: "n"(n) : "memory")

__device__ __forceinline__ uint4 ldmx4(unsigned a){
    uint4 r;
    asm volatile("ldmatrix.sync.aligned.m8n8.x4.shared.b16 {%0,%1,%2,%3}, [%4];"
        : "=r"(r.x), "=r"(r.y), "=r"(r.z), "=r"(r.w) : "r"(a));
    return r;
}

// ---------------------------------------------------------------------------
// LN1 + sigma (xn stored bf16), with round_w blocks packed in.
// blocks [0,16384): LN1 rows.  blocks [16384,17408): weight conversion.
// ---------------------------------------------------------------------------
__global__ void ln1_sigma_roundw_kernel(const float* __restrict__ x,
                                        const float* __restrict__ g,
                                        const float* __restrict__ b,
                                        const float* __restrict__ Wsig,
                                        const float* __restrict__ w0,
                                        const float* __restrict__ w1,
                                        const float* __restrict__ w2,
                                        const float* __restrict__ w3)
{
    int tid = threadIdx.x;
    if (blockIdx.x >= MROWS){
        int i = (blockIdx.x - MROWS) * 256 + tid;
        g_wh[i]         = __float2bfloat16(w0[i]);
        g_wh[i +   WSZ] = __float2bfloat16(w1[i]);
        g_wh[i + 2*WSZ] = __float2bfloat16(w2[i]);
        g_wr[i]         = tf32r(w3[i]);
        return;
    }
    int row = blockIdx.x;
    int warp = tid >> 5, lane = tid & 31;
    const float* xr = x + (size_t)row * DDIM;
    float x0 = xr[tid], x1 = xr[tid + 256];
    float s = x0 + x1, sq = x0*x0 + x1*x1;
    #pragma unroll
    for (int o = 16; o > 0; o >>= 1) {
        s  += __shfl_xor_sync(~0u, s,  o);
        sq += __shfl_xor_sync(~0u, sq, o);
    }
    __shared__ float sm[8], sm2[8];
    if (lane == 0) { sm[warp] = s; sm2[warp] = sq; }
    __syncthreads();
    float tot = 0.f, tot2 = 0.f;
    #pragma unroll
    for (int i = 0; i < 8; i++) { tot += sm[i]; tot2 += sm2[i]; }
    float mean = tot * (1.f / DDIM);
    float var  = tot2 * (1.f / DDIM) - mean * mean;
    float rstd = rsqrtf(var + 1e-5f);
    g_xnh[(size_t)row*DDIM + tid]       = __float2bfloat16((x0 - mean) * rstd * g[tid]       + b[tid]);
    g_xnh[(size_t)row*DDIM + tid + 256] = __float2bfloat16((x1 - mean) * rstd * g[tid + 256] + b[tid + 256]);

    float acc[HH];
    #pragma unroll
    for (int h = 0; h < HH; h++)
        acc[h] = x0 * Wsig[tid*HH + h] + x1 * Wsig[(tid+256)*HH + h];
    #pragma unroll
    for (int h = 0; h < HH; h++)
        #pragma unroll
        for (int o = 16; o > 0; o >>= 1)
            acc[h] += __shfl_xor_sync(~0u, acc[h], o);
    __shared__ float red[8][HH];
    if (lane == 0)
        #pragma unroll
        for (int h = 0; h < HH; h++) red[warp][h] = acc[h];
    __syncthreads();
    if (tid < HH) {
        float z = 0.f;
        #pragma unroll
        for (int w = 0; w < 8; w++) z += red[w][tid];
        float sg  = 1.f / (1.f + expf(-5.f * z)) + 1e-5f;
        float sig = exp2f(sg * 1.5849625007211562f) - 1.f;   // 3^sg - 1
        int bb = row / TT, t = row % TT;
        g_sigma[(bb*HH + tid)*TT + t] = sig;
    }
}

// ---------------------------------------------------------------------------
// bf16 NT GEMM for QKV: C = A[16384,512] @ W[1536,512]^T, BK=64 elements.
// 128x128 tiles, 256 thr (2m x 4n warps), 3-stage cp.async, HROW=144B rows.
// Epilogue routing: n0<512 -> Q bf16, <1024 -> K bf16, else V tf32 transposed.
// ---------------------------------------------------------------------------
__global__ void __launch_bounds__(256,2)
bf16_gemm_qkv(const __nv_bfloat16* __restrict__ A,
              const __nv_bfloat16* __restrict__ Bw,
              __nv_bfloat16* __restrict__ Cq, __nv_bfloat16* __restrict__ Ck,
              float* __restrict__ Cv)
{
    constexpr int HROW = 144;              // 64 bf16 = 128B + 16B pad
    constexpr int STG  = 128*HROW;         // 18432 B per operand stage

    extern __shared__ float dsm[];
    const unsigned sb = (unsigned)__cvta_generic_to_shared(dsm);
    const unsigned aS = sb;
    const unsigned bS = sb + 3*STG;

    const int tid  = threadIdx.x;
    const int lane = tid & 31;
    const int wid  = tid >> 5;
    const int wm   = wid & 1;
    const int wn   = wid >> 1;
    const int g    = lane >> 2;
    const int t    = lane & 3;

    const int m0 = blockIdx.y * 128;
    const int n0 = blockIdx.x * 128;

    auto issue = [&](int st, int k0){
        unsigned ab = aS + st*STG, bb = bS + st*STG;
        #pragma unroll
        for (int e = 0; e < 4; e++){
            int idx2 = tid + 256*e;           // 0..1023
            int r = idx2 >> 3, c8 = idx2 & 7; // 128 rows x 8 16B-units
            cp16(ab + (unsigned)(r*HROW + c8*16), A  + (long)(m0 + r)*512 + k0 + c8*8);
            cp16(bb + (unsigned)(r*HROW + c8*16), Bw + (long)(n0 + r)*512 + k0 + c8*8);
        }
    };

    // bf16 fragment offsets (bytes) — same map as proven mega QK phase
    const int arow = (lane & 7) + ((lane >> 3) & 1) * 8;
    const unsigned aFh = (unsigned)((wm*64 + arow)*HROW + (lane >> 4)*16);
    const unsigned bFh = (unsigned)((wn*32 + (lane & 7) + ((lane >> 4) & 1)*8)*HROW
                                    + ((lane >> 3) & 1)*16);

    float acc[4][4][4];
    #pragma unroll
    for (int i = 0; i < 4; i++)
        #pragma unroll
        for (int j = 0; j < 4; j++)
            #pragma unroll
            for (int p = 0; p < 4; p++) acc[i][j][p] = 0.f;

    issue(0, 0);  CPCOMMIT();
    issue(1, 64); CPCOMMIT();

    int buf = 0;
    for (int k0 = 0; k0 < 512; k0 += 64) {
        CPWAIT(1);
        __syncthreads();
        if (k0 + 128 < 512) {
            int nb = buf + 2; if (nb >= 3) nb -= 3;
            issue(nb, k0 + 128);
        }
        CPCOMMIT();

        const unsigned ab = aS + buf*STG;
        const unsigned bb = bS + buf*STG;

        uint4 bfr[2][4];
        #pragma unroll
        for (int ntp = 0; ntp < 2; ntp++)
            #pragma unroll
            for (int ks = 0; ks < 4; ks++)
                bfr[ntp][ks] = ldmx4(bb + bFh + (unsigned)(ntp*16*HROW + ks*32));

        #pragma unroll
        for (int ks = 0; ks < 4; ks++){
            #pragma unroll
            for (int mt = 0; mt < 4; mt++){
                uint4 a = ldmx4(ab + aFh + (unsigned)(mt*16*HROW + ks*32));
                #pragma unroll
                for (int ntp = 0; ntp < 2; ntp++){
                    mma16bf(acc[mt][2*ntp],   a.x, a.y, a.z, a.w,
                            bfr[ntp][ks].x, bfr[ntp][ks].y);
                    mma16bf(acc[mt][2*ntp+1], a.x, a.y, a.z, a.w,
                            bfr[ntp][ks].z, bfr[ntp][ks].w);
                }
            }
        }
        buf++; if (buf == 3) buf = 0;
    }

    // Epilogue
    #pragma unroll
    for (int mt = 0; mt < 4; mt++){
        #pragma unroll
        for (int nt = 0; nt < 4; nt++){
            int row = m0 + wm*64 + mt*16 + g;
            int col = n0 + wn*32 + nt*8 + 2*t;
            float v0 = acc[mt][nt][0], v1 = acc[mt][nt][1];
            float v2 = acc[mt][nt][2], v3 = acc[mt][nt][3];
            if (n0 < 512){
                __nv_bfloat162 h0, h1;
                h0.x = __float2bfloat16(v0); h0.y = __float2bfloat16(v1);
                h1.x = __float2bfloat16(v2); h1.y = __float2bfloat16(v3);
                *(__nv_bfloat162*)&Cq[(long)row*512 + col]     = h0;
                *(__nv_bfloat162*)&Cq[(long)(row+8)*512 + col] = h1;
            } else if (n0 < 1024){
                int c2 = col - 512;
                __nv_bfloat162 h0, h1;
                h0.x = __float2bfloat16(v0); h0.y = __float2bfloat16(v1);
                h1.x = __float2bfloat16(v2); h1.y = __float2bfloat16(v3);
                *(__nv_bfloat162*)&Ck[(long)row*512 + c2]     = h0;
                *(__nv_bfloat162*)&Ck[(long)(row+8)*512 + c2] = h1;
            } else {
                int vc = col - 1024;
                long base0 = (long)(row >> 9) * (512L*512) + (row & 511);
                Cv[base0 + (long)vc*512]         = tf32r(v0);
                Cv[base0 + (long)(vc+1)*512]     = tf32r(v1);
                Cv[base0 + 8 + (long)vc*512]     = tf32r(v2);
                Cv[base0 + 8 + (long)(vc+1)*512] = tf32r(v3);
            }
        }
    }
}

// ---------------------------------------------------------------------------
// tf32 NT GEMM (out-proj): C = A@B^T + bias + res.  BK=32, 3-stage.
// ---------------------------------------------------------------------------
__global__ void __launch_bounds__(256,2)
tf32_gemm_out(const float* __restrict__ A, const float* __restrict__ Bw,
              float* __restrict__ C,
              const float* __restrict__ bias, const float* __restrict__ res)
{
    constexpr int ST  = 36;
    constexpr int STG = 128*ST*4;

    extern __shared__ float dsm[];
    const unsigned sb = (unsigned)__cvta_generic_to_shared(dsm);
    const unsigned aS = sb;
    const unsigned bS = sb + 3*STG;

    const int tid  = threadIdx.x;
    const int lane = tid & 31;
    const int wid  = tid >> 5;
    const int wm   = wid & 1;
    const int wn   = wid >> 1;
    const int g    = lane >> 2;
    const int t    = lane & 3;

    const int m0 = blockIdx.y * 128;
    const int n0 = blockIdx.x * 128;

    const int rl = tid >> 3;
    const int qc = tid & 7;

    const float* Ag = A  + (long)(m0 + rl) * 512 + qc*4;
    const float* Bg = Bw + (long)(n0 + rl) * 512 + qc*4;
    const unsigned dA = (unsigned)(rl*ST + qc*4) * 4;

    auto issue = [&](int st, int k0){
        unsigned ab = aS + st*STG, bb = bS + st*STG;
        #pragma unroll
        for (int e = 0; e < 4; e++){
            cp16(ab + dA + e*32*ST*4, Ag + (long)e*32*512 + k0);
            cp16(bb + dA + e*32*ST*4, Bg + (long)e*32*512 + k0);
        }
    };

    const int arow = (lane & 7) + ((lane >> 3) & 1) * 8;
    const int acol = (lane >> 4) * 4;
    const unsigned aFB = (unsigned)((wm*64 + arow)*ST + acol) * 4;
    const unsigned bFB = (unsigned)((wn*32 + (lane & 7))*ST + (lane >> 3)*4) * 4;

    float acc[4][4][4];
    #pragma unroll
    for (int i = 0; i < 4; i++)
        #pragma unroll
        for (int j = 0; j < 4; j++)
            #pragma unroll
            for (int p = 0; p < 4; p++) acc[i][j][p] = 0.f;

    issue(0, 0);  CPCOMMIT();
    issue(1, 32); CPCOMMIT();

    int buf = 0;
    for (int k0 = 0; k0 < 512; k0 += 32) {
        CPWAIT(1);
        __syncthreads();
        if (k0 + 64 < 512) {
            int nb = buf + 2; if (nb >= 3) nb -= 3;
            issue(nb, k0 + 64);
        }
        CPCOMMIT();

        const unsigned ab = aS + buf*STG;
        const unsigned bb = bS + buf*STG;

        uint4 bfr[4][2];
        #pragma unroll
        for (int nt = 0; nt < 4; nt++)
            #pragma unroll
            for (int kg = 0; kg < 2; kg++)
                bfr[nt][kg] = ldmx4(bb + bFB + (unsigned)(nt*8*ST + kg*16)*4);

        #pragma unroll
        for (int ks = 0; ks < 4; ks++) {
            #pragma unroll
            for (int mt = 0; mt < 4; mt++) {
                uint4 a = ldmx4(ab + aFB + (unsigned)(mt*16*ST + ks*8)*4);
                #pragma unroll
                for (int nt = 0; nt < 4; nt++)
                    mma8(acc[mt][nt], a.x, a.y, a.z, a.w,
                         (ks & 1) ? bfr[nt][ks>>1].z : bfr[nt][ks>>1].x,
                         (ks & 1) ? bfr[nt][ks>>1].w : bfr[nt][ks>>1].y);
            }
        }
        buf++; if (buf == 3) buf = 0;
    }

    #pragma unroll
    for (int mt = 0; mt < 4; mt++){
        #pragma unroll
        for (int nt = 0; nt < 4; nt++){
            int row = m0 + wm*64 + mt*16 + g;
            int col = n0 + wn*32 + nt*8 + 2*t;
            float v0 = acc[mt][nt][0] + bias[col]   + res[(long)row*512 + col];
            float v1 = acc[mt][nt][1] + bias[col+1] + res[(long)row*512 + col+1];
            float v2 = acc[mt][nt][2] + bias[col]   + res[(long)(row+8)*512 + col];
            float v3 = acc[mt][nt][3] + bias[col+1] + res[(long)(row+8)*512 + col+1];
            *(float2*)&C[(long)row*512 + col]     = make_float2(v0, v1);
            *(float2*)&C[(long)(row+8)*512 + col] = make_float2(v2, v3);
        }
    }
}

// ---------------------------------------------------------------------------
// MEGA kernel: attention (bf16 QK + tf32 AV) + prior + style (proven r11).
// ---------------------------------------------------------------------------
__global__ void __launch_bounds__(256,2)
mega_attn_kernel(const __nv_bfloat16* __restrict__ Q,
                 const __nv_bfloat16* __restrict__ Kt,
                 const float* __restrict__ Vt,
                 float* __restrict__ S, float* __restrict__ Y,
                 float* __restrict__ prior, float* __restrict__ sfull,
                 const float* __restrict__ emb,
                 const float* __restrict__ embW,
                 const float* __restrict__ embB)
{
    extern __shared__ float dsm[];
    const int tid  = threadIdx.x;
    const unsigned bx = blockIdx.x;

    // ---------------- style blocks ----------------
    if (bx >= 8192){
        int sb = bx - 8192;
        int bb = sb >> 2, part = sb & 3;
        float* se = dsm;
        for (int i = tid; i < TEDIM; i += 256){
            float e = emb[(size_t)bb * TEDIM + i];
            se[i] = siluf(e);
        }
        __syncthreads();
        int j = part*256 + tid;
        float acc = 0.f;
        for (int k = 0; k < TEDIM; k++)
            acc += se[k] * embW[(size_t)k * (2*DDIM) + j];
        g_style[bb * (2*DDIM) + j] = acc + embB[j];
        return;
    }

    // ---------------- prior blocks ----------------
    if (bx & 1){
        long base = (long)(bx >> 1) * 32;
        int w = tid >> 5, l = tid & 31;
        #pragma unroll
        for (int i = 0; i < 4; i++){
            long row = base + w*4 + i;
            int n = (int)(row & 511);
            float s = g_sigma[row];
            float inv2 = -1.f / (2.f * s * s);
            float coef = 0.3989422804014327f / s;
            float4 sv = make_float4(s, s, s, s);
            float4* pp = (float4*)(prior + row * TT);
            float4* sp = (float4*)(sfull + row * TT);
            #pragma unroll
            for (int j = 0; j < 4; j++){
                int c4 = l + j*32;
                int m = c4 * 4;
                float d0 = (float)(n - m);
                float d1 = (float)(n - (m+1));
                float d2 = (float)(n - (m+2));
                float d3 = (float)(n - (m+3));
                float4 pv;
                pv.x = __expf(d0*d0*inv2) * coef;
                pv.y = __expf(d1*d1*inv2) * coef;
                pv.z = __expf(d2*d2*inv2) * coef;
                pv.w = __expf(d3*d3*inv2) * coef;
                pp[c4] = pv;
                sp[c4] = sv;
            }
        }
        return;
    }

    // ---------------- attention blocks ----------------
    const int idx = bx >> 1;
    const int bh = idx >> 4;          // b*8+h
    const int m0 = (idx & 15) * 32;

    constexpr int VST = 132;          // V row stride (floats)
    constexpr int SST = 132;          // series staging stride (floats)
    constexpr int HROW = 144;         // bf16 tile row stride (bytes)
    const unsigned A_BYTES = 8704;
    const unsigned B_BYTES = 34816;

    const unsigned sb  = (unsigned)__cvta_generic_to_shared(dsm);
    const unsigned sbA = sb;
    const unsigned sbB = sb + A_BYTES;
    const unsigned sbS = sb + A_BYTES + 2*B_BYTES;       // series chunk 32x132
    float* red = dsm + (A_BYTES + 2*B_BYTES)/4 + 32*SST; // [32][4]

    const int lane = tid & 31;
    const int wid  = tid >> 5;
    const int wm   = wid & 1;
    const int wn   = wid >> 1;        // 0..3
    const int g    = lane >> 2;
    const int t    = lane & 3;

    const int b  = bh >> 3, h = bh & 7;

    const __nv_bfloat16* Qb = Q + ((long)b*512 + m0)*512 + h*64;
    const __nv_bfloat16* Kb = Kt + ((long)b*512)*512 + h*64;
    const float* Vb = Vt + (long)b*(512L*512) + (long)h*64*512; // [64 d][512 t]
    float* Sb = S + ((long)bh*512 + m0)*512;
    float* Yb = Y + ((long)b*512)*512 + h*64;

    const int arow = (lane & 7) + ((lane >> 3) & 1) * 8;
    const unsigned aFh = sbA + (unsigned)((wm*16 + arow)*HROW + (lane >> 4)*16);
    const unsigned bFh0 = (unsigned)((wn*32 + (lane & 7) + ((lane >> 4) & 1)*8)*HROW
                                     + ((lane >> 3) & 1)*16);
    const unsigned bFh1 = bFh0 + (unsigned)(16*HROW);

    const unsigned sF  = sbS + (unsigned)((wm*16 + arow)*SST + (lane >> 4)*4) * 4;
    const unsigned vF  = (unsigned)((wn*16 + (lane & 7))*VST + (lane >> 3)*4) * 4;

    auto issueB = [&](int chunk, int bufb){
        unsigned dst = sbB + (unsigned)bufb * B_BYTES;
        const __nv_bfloat16* src = Kb + (long)(chunk*128)*512;
        #pragma unroll
        for (int e = 0; e < 4; e++){
            int idx2 = tid + 256*e;
            int r = idx2 >> 3, c8 = idx2 & 7;
            cp16(dst + (unsigned)(r*HROW + c8*16), src + (long)r*512 + c8*8);
        }
    };
    auto issueV = [&](int chunk, int bufb){
        unsigned dst = sbB + (unsigned)bufb * B_BYTES;
        #pragma unroll
        for (int e = 0; e < 8; e++){
            int idx2 = tid + 256*e;
            int r  = idx2 >> 5;
            int qc = idx2 & 31;
            cp16(dst + (unsigned)(r*VST + qc*4)*4,
                 Vb + (long)r*512 + chunk*128 + qc*4);
        }
    };

    // group 0: Q tile (bf16) + K chunk 0
    {
        int r = tid >> 3, c8 = tid & 7;
        cp16(sbA + (unsigned)(r*HROW + c8*16), Qb + (long)r*512 + c8*8);
        issueB(0, 0);
        CPCOMMIT();
    }

    float acc[4][4][4];
    #pragma unroll
    for (int c = 0; c < 4; c++)
        #pragma unroll
        for (int nt = 0; nt < 4; nt++)
            #pragma unroll
            for (int p = 0; p < 4; p++) acc[c][nt][p] = 0.f;

    for (int c = 0; c < 4; c++){
        CPWAIT(0);
        __syncthreads();
        if (c + 1 < 4) issueB(c + 1, (c + 1) & 1);
        CPCOMMIT();

        const unsigned bb2 = sbB + (unsigned)(c & 1) * B_BYTES;
        #pragma unroll
        for (int ks = 0; ks < 4; ks++){
            uint4 a = ldmx4(aFh + (unsigned)(ks*32));
            uint4 bv0 = ldmx4(bb2 + bFh0 + (unsigned)(ks*32));
            mma16bf(acc[c][0], a.x, a.y, a.z, a.w, bv0.x, bv0.y);
            mma16bf(acc[c][1], a.x, a.y, a.z, a.w, bv0.z, bv0.w);
            uint4 bv1 = ldmx4(bb2 + bFh1 + (unsigned)(ks*32));
            mma16bf(acc[c][2], a.x, a.y, a.z, a.w, bv1.x, bv1.y);
            mma16bf(acc[c][3], a.x, a.y, a.z, a.w, bv1.z, bv1.w);
        }
    }
    __syncthreads();                      // protect V prefetch overwriting buf 1

    issueV(0, 0); CPCOMMIT();
    issueV(1, 1); CPCOMMIT();

    #pragma unroll
    for (int c = 0; c < 4; c++)
        #pragma unroll
        for (int nt = 0; nt < 4; nt++)
            #pragma unroll
            for (int p = 0; p < 4; p++) acc[c][nt][p] *= (1.f/64.f);

    const int r0 = wm*16 + g, r1 = r0 + 8;

    float mx0 = -1e30f, mx1 = -1e30f;
    #pragma unroll
    for (int c = 0; c < 4; c++)
        #pragma unroll
        for (int nt = 0; nt < 4; nt++){
            mx0 = fmaxf(mx0, fmaxf(acc[c][nt][0], acc[c][nt][1]));
            mx1 = fmaxf(mx1, fmaxf(acc[c][nt][2], acc[c][nt][3]));
        }
    #pragma unroll
    for (int o = 1; o <= 2; o <<= 1){
        mx0 = fmaxf(mx0, __shfl_xor_sync(~0u, mx0, o));
        mx1 = fmaxf(mx1, __shfl_xor_sync(~0u, mx1, o));
    }
    if (t == 0){ red[r0*4 + wn] = mx0; red[r1*4 + wn] = mx1; }
    __syncthreads();
    float rm0 = fmaxf(fmaxf(red[r0*4+0], red[r0*4+1]), fmaxf(red[r0*4+2], red[r0*4+3]));
    float rm1 = fmaxf(fmaxf(red[r1*4+0], red[r1*4+1]), fmaxf(red[r1*4+2], red[r1*4+3]));
    __syncthreads();

    float s0 = 0.f, s1 = 0.f;
    #pragma unroll
    for (int c = 0; c < 4; c++)
        #pragma unroll
        for (int nt = 0; nt < 4; nt++){
            acc[c][nt][0] = __expf(acc[c][nt][0] - rm0);
            acc[c][nt][1] = __expf(acc[c][nt][1] - rm0);
            acc[c][nt][2] = __expf(acc[c][nt][2] - rm1);
            acc[c][nt][3] = __expf(acc[c][nt][3] - rm1);
            s0 += acc[c][nt][0] + acc[c][nt][1];
            s1 += acc[c][nt][2] + acc[c][nt][3];
        }
    #pragma unroll
    for (int o = 1; o <= 2; o <<= 1){
        s0 += __shfl_xor_sync(~0u, s0, o);
        s1 += __shfl_xor_sync(~0u, s1, o);
    }
    if (t == 0){ red[r0*4 + wn] = s0; red[r1*4 + wn] = s1; }
    __syncthreads();
    float inv0 = 1.f / (red[r0*4+0] + red[r0*4+1] + red[r0*4+2] + red[r0*4+3]);
    float inv1 = 1.f / (red[r1*4+0] + red[r1*4+1] + red[r1*4+2] + red[r1*4+3]);

    float yacc[2][4];
    #pragma unroll
    for (int nt = 0; nt < 2; nt++)
        #pragma unroll
        for (int p = 0; p < 4; p++) yacc[nt][p] = 0.f;

    float* Srow0 = dsm + (A_BYTES + 2*B_BYTES)/4;
    float* p0 = Sb + (long)r0*512;
    float* p1 = Sb + (long)r1*512;

    #pragma unroll
    for (int c = 0; c < 4; c++){
        #pragma unroll
        for (int nt = 0; nt < 4; nt++){
            int colc = wn*32 + nt*8 + 2*t;
            float n00 = acc[c][nt][0]*inv0, n01 = acc[c][nt][1]*inv0;
            float n10 = acc[c][nt][2]*inv1, n11 = acc[c][nt][3]*inv1;
            Srow0[r0*SST + colc]   = tf32r(n00);
            Srow0[r0*SST + colc+1] = tf32r(n01);
            Srow0[r1*SST + colc]   = tf32r(n10);
            Srow0[r1*SST + colc+1] = tf32r(n11);
            *(float2*)&p0[c*128 + colc] = make_float2(n00, n01);
            *(float2*)&p1[c*128 + colc] = make_float2(n10, n11);
        }
        if (c < 3) { CPWAIT(1); } else { CPWAIT(0); }
        __syncthreads();

        const unsigned vb = sbB + (unsigned)(c & 1) * B_BYTES;
        #pragma unroll
        for (int kg = 0; kg < 8; kg++){
            uint4 a0 = ldmx4(sF + (unsigned)(kg*16 + 0)*4);
            uint4 a1 = ldmx4(sF + (unsigned)(kg*16 + 8)*4);
            #pragma unroll
            for (int nt = 0; nt < 2; nt++){
                uint4 bv = ldmx4(vb + vF + (unsigned)(nt*8*VST + kg*16)*4);
                mma8(yacc[nt], a0.x, a0.y, a0.z, a0.w, bv.x, bv.y);
                mma8(yacc[nt], a1.x, a1.y, a1.z, a1.w, bv.z, bv.w);
            }
        }
        __syncthreads();
        if (c + 2 < 4){ issueV(c + 2, c & 1); }
        CPCOMMIT();
    }

    #pragma unroll
    for (int nt = 0; nt < 2; nt++){
        int col = wn*16 + nt*8 + 2*t;
        int rowA = m0 + r0, rowB = m0 + r1;
        *(float2*)&Yb[(long)rowA*512 + col] = make_float2(yacc[nt][0], yacc[nt][1]);
        *(float2*)&Yb[(long)rowB*512 + col] = make_float2(yacc[nt][2], yacc[nt][3]);
    }
}

// ---------------------------------------------------------------------------
// LN2 + scale/shift + silu (hs stored tf32-rounded)
// ---------------------------------------------------------------------------
__global__ void ln2_style_kernel(const float* __restrict__ g,
                                 const float* __restrict__ b)
{
    int row = blockIdx.x;
    int tid = threadIdx.x;
    int warp = tid >> 5, lane = tid & 31;
    int bb = row / TT;
    const float* yr = g_y + (size_t)row * DDIM;
    float x0 = yr[tid], x1 = yr[tid + 256];
    float s = x0 + x1, sq = x0*x0 + x1*x1;
    #pragma unroll
    for (int o = 16; o > 0; o >>= 1) {
        s  += __shfl_xor_sync(~0u, s,  o);
        sq += __shfl_xor_sync(~0u, sq, o);
    }
    __shared__ float sm[8], sm2[8];
    if (lane == 0) { sm[warp] = s; sm2[warp] = sq; }
    __syncthreads();
    float tot = 0.f, tot2 = 0.f;
    #pragma unroll
    for (int i = 0; i < 8; i++) { tot += sm[i]; tot2 += sm2[i]; }
    float mean = tot * (1.f / DDIM);
    float var  = tot2 * (1.f / DDIM) - mean * mean;
    float rstd = rsqrtf(var + 1e-5f);
    float n0 = (x0 - mean) * rstd * g[tid]       + b[tid];
    float n1 = (x1 - mean) * rstd * g[tid + 256] + b[tid + 256];
    const float* st = g_style + bb * (2*DDIM);
    float h0 = n0 * (1.f + st[tid])       + st[512 + tid];
    float h1 = n1 * (1.f + st[tid + 256]) + st[512 + tid + 256];
    g_hs[(size_t)row*DDIM + tid]       = tf32r(siluf(h0));
    g_hs[(size_t)row*DDIM + tid + 256] = tf32r(siluf(h1));
}

// ---------------------------------------------------------------------------
extern "C" void kernel_launch(void* const* d_in, const int* in_sizes, int n_in,
                              void* d_out, int out_size)
{
    const float* x    = (const float*)d_in[0];
    const float* emb  = (const float*)d_in[1];
    const float* Wq   = (const float*)d_in[2];
    const float* Wk   = (const float*)d_in[3];
    const float* Wv   = (const float*)d_in[4];
    const float* Wsig = (const float*)d_in[5];
    const float* ln1g = (const float*)d_in[6];
    const float* ln1b = (const float*)d_in[7];
    const float* embW = (const float*)d_in[8];
    const float* embB = (const float*)d_in[9];
    const float* ln2g = (const float*)d_in[10];
    const float* ln2b = (const float*)d_in[11];
    const float* outW = (const float*)d_in[12];
    const float* outB = (const float*)d_in[13];

    float* out    = (float*)d_out;
    float* outY   = out;
    float* outS   = out + YN;
    float* outP   = outS + SN;
    float* outSig = outP + SN;

    float *pv, *py, *phs, *pwr;
    __nv_bfloat16 *pxnh, *pqh, *pkh, *pwh;
    cudaGetSymbolAddress((void**)&pxnh, g_xnh);
    cudaGetSymbolAddress((void**)&pqh, g_qh);
    cudaGetSymbolAddress((void**)&pkh, g_kh);
    cudaGetSymbolAddress((void**)&pwh, g_wh);
    cudaGetSymbolAddress((void**)&pv,  g_v);
    cudaGetSymbolAddress((void**)&py,  g_y);
    cudaGetSymbolAddress((void**)&phs, g_hs);
    cudaGetSymbolAddress((void**)&pwr, g_wr);

    const int SMG = 3*2*128*36*4;                            // 110592
    const int SMH = 3*2*128*144;                             // 110592
    const int SMF = 8704 + 2*34816 + 32*132*4 + 512;         // 95744

    cudaFuncSetAttribute(bf16_gemm_qkv,     cudaFuncAttributeMaxDynamicSharedMemorySize, SMH);
    cudaFuncSetAttribute(tf32_gemm_out,     cudaFuncAttributeMaxDynamicSharedMemorySize, SMG);
    cudaFuncSetAttribute(mega_attn_kernel,  cudaFuncAttributeMaxDynamicSharedMemorySize, SMF);

    // 1) LN1 + sigma + weight conversion (packed)
    ln1_sigma_roundw_kernel<<<MROWS + WSZ/256, 256>>>(
        x, ln1g, ln1b, Wsig, Wq, Wk, Wv, outW);

    // 2) merged QKV projection in bf16 (Q/K -> bf16, V -> tf32 transposed)
    bf16_gemm_qkv<<<dim3(12, MROWS/128), 256, SMH>>>(
        pxnh, pwh, pqh, pkh, pv);

    // 3) MEGA: attention (bf16 QK + tf32 AV) + prior + sigma_full + style
    mega_attn_kernel<<<8192 + 128, 256, SMF>>>(
        pqh, pkh, pv, outS, py, outP, outSig, emb, embW, embB);

    // 4) LN2 + style + silu
    ln2_style_kernel<<<MROWS, 256>>>(ln2g, ln2b);

    // 5) y_out = x + silu_h @ out_W^T + out_b
    tf32_gemm_out<<<dim3(4, MROWS/128), 256, SMG>>>(
        phs, pwr, outY, outB, x);
}

// round 14
// speedup vs baseline: 1.3058x; 1.0579x over previous
#include <cuda_runtime.h>
#include <cuda_bf16.h>

// Problem constants
#define BQ   32
#define TT   512
#define DDIM 512
#define HH   8
#define HD   64
#define TEDIM 2048
#define MROWS (BQ*TT)            // 16384
#define YN ((size_t)BQ*TT*DDIM)  // 8388608
#define SN ((size_t)BQ*HH*TT*TT) // 67108864
#define WSZ (DDIM*DDIM)          // 262144

// Scratch (device globals — no allocation allowed)
__device__ __nv_bfloat16 g_xnh[BQ*TT*DDIM];  // LN1 output, bf16
__device__ __nv_bfloat16 g_qh[BQ*TT*DDIM];   // Q in bf16
__device__ __nv_bfloat16 g_kh[BQ*TT*DDIM];   // K in bf16
__device__ float g_v [BQ*TT*DDIM];   // stored TRANSPOSED: [b][h*64+d][t] (tf32)
__device__ float g_y [BQ*TT*DDIM];
__device__ float g_hs[BQ*TT*DDIM];   // LN2/silu output, tf32-rounded fp32
__device__ float g_sigma[BQ*HH*TT];
__device__ float g_style[BQ*2*DDIM];
__device__ __nv_bfloat16 g_wh[3*WSZ];        // bf16 [Wq;Wk;Wv] (1536x512)
__device__ float g_wr[WSZ];                  // tf32-rounded outW

__device__ __forceinline__ float siluf(float z){ return z / (1.f + expf(-z)); }

__device__ __forceinline__ float tf32r(float f){
    unsigned u; asm("cvt.rna.tf32.f32 %0, %1;" : "=r"(u) : "f"(f));
    return __uint_as_float(u);
}

__device__ __forceinline__ void mma8(float* c,
    unsigned a0, unsigned a1, unsigned a2, unsigned a3,
    unsigned b0, unsigned b1)
{
    asm volatile(
        "mma.sync.aligned.m16n8k8.row.col.f32.tf32.tf32.f32 "
        "{%0,%1,%2,%3}, {%4,%5,%6,%7}, {%8,%9}, {%0,%1,%2,%3};"
        : "+f"(c[0]), "+f"(c[1]), "+f"(c[2]), "+f"(c[3])
        : "r"(a0), "r"(a1), "r"(a2), "r"(a3), "r"(b0), "r"(b1));
}

__device__ __forceinline__ void mma16bf(float* c,
    unsigned a0, unsigned a1, unsigned a2, unsigned a3,
    unsigned b0, unsigned b1)
{
    asm volatile(
        "mma.sync.aligned.m16n8k16.row.col.f32.bf16.bf16.f32 "
        "{%0,%1,%2,%3}, {%4,%5,%6,%7}, {%8,%9}, {%0,%1,%2,%3};"
        : "+f"(c[0]), "+f"(c[1]), "+f"(c[2]), "+f"(c[3])
        : "r"(a0), "r"(a1), "r"(a2), "r"(a3), "r"(b0), "r"(b1));
}

__device__ __forceinline__ void cp16(unsigned dst, const void* src){
    asm volatile("cp.async.cg.shared.global [%0], [%1], 16;" :: "r"(dst), "l"(src));
}
#define CPCOMMIT() asm volatile("cp.async.commit_group;" ::: "memory")
#define CPWAIT(n)  asm volatile("cp.async.wait_group %0;" :: "n"(n) : "memory")

__device__ __forceinline__ uint4 ldmx4(unsigned a){
    uint4 r;
    asm volatile("ldmatrix.sync.aligned.m8n8.x4.shared.b16 {%0,%1,%2,%3}, [%4];"
        : "=r"(r.x), "=r"(r.y), "=r"(r.z), "=r"(r.w) : "r"(a));
    return r;
}

// ---------------------------------------------------------------------------
// LN1 + sigma, WARP-PER-ROW (8 rows/block, no block barriers), plus weight
// conversion blocks packed in.
// blocks [0,2048): 8 LN rows each.  blocks [2048,3072): weight conversion.
// ---------------------------------------------------------------------------
__global__ void __launch_bounds__(256)
ln1_sigma_roundw_kernel(const float* __restrict__ x,
                        const float* __restrict__ g,
                        const float* __restrict__ b,
                        const float* __restrict__ Wsig,
                        const float* __restrict__ w0,
                        const float* __restrict__ w1,
                        const float* __restrict__ w2,
                        const float* __restrict__ w3)
{
    int tid = threadIdx.x;
    if (blockIdx.x >= 2048){
        int i = (blockIdx.x - 2048) * 256 + tid;
        g_wh[i]         = __float2bfloat16(w0[i]);
        g_wh[i +   WSZ] = __float2bfloat16(w1[i]);
        g_wh[i + 2*WSZ] = __float2bfloat16(w2[i]);
        g_wr[i]         = tf32r(w3[i]);
        return;
    }
    const int warp = tid >> 5, lane = tid & 31;
    const int row  = blockIdx.x * 8 + warp;
    const float4* xr = (const float4*)(x + (size_t)row * DDIM);

    float4 v[4];
    float s = 0.f, sq = 0.f;
    #pragma unroll
    for (int i = 0; i < 4; i++){
        v[i] = xr[lane + 32*i];
        s  += v[i].x + v[i].y + v[i].z + v[i].w;
        sq += v[i].x*v[i].x + v[i].y*v[i].y + v[i].z*v[i].z + v[i].w*v[i].w;
    }
    #pragma unroll
    for (int o = 16; o > 0; o >>= 1){
        s  += __shfl_xor_sync(~0u, s,  o);
        sq += __shfl_xor_sync(~0u, sq, o);
    }
    float mean = s * (1.f / DDIM);
    float var  = sq * (1.f / DDIM) - mean * mean;
    float rstd = rsqrtf(var + 1e-5f);

    float acc[HH];
    #pragma unroll
    for (int h = 0; h < HH; h++) acc[h] = 0.f;

    #pragma unroll
    for (int i = 0; i < 4; i++){
        int c = (lane + 32*i) * 4;
        float4 g4 = ((const float4*)g)[lane + 32*i];
        float4 b4 = ((const float4*)b)[lane + 32*i];
        float n0 = (v[i].x - mean)*rstd*g4.x + b4.x;
        float n1 = (v[i].y - mean)*rstd*g4.y + b4.y;
        float n2 = (v[i].z - mean)*rstd*g4.z + b4.z;
        float n3 = (v[i].w - mean)*rstd*g4.w + b4.w;
        __nv_bfloat162 h01, h23;
        h01.x = __float2bfloat16(n0); h01.y = __float2bfloat16(n1);
        h23.x = __float2bfloat16(n2); h23.y = __float2bfloat16(n3);
        *(__nv_bfloat162*)&g_xnh[(size_t)row*DDIM + c]     = h01;
        *(__nv_bfloat162*)&g_xnh[(size_t)row*DDIM + c + 2] = h23;

        // sigma dots use RAW x
        const float* el = (const float*)&v[i];
        #pragma unroll
        for (int j = 0; j < 4; j++){
            float4 wlo = ((const float4*)Wsig)[(c + j)*2];
            float4 whi = ((const float4*)Wsig)[(c + j)*2 + 1];
            float e = el[j];
            acc[0] += e*wlo.x; acc[1] += e*wlo.y; acc[2] += e*wlo.z; acc[3] += e*wlo.w;
            acc[4] += e*whi.x; acc[5] += e*whi.y; acc[6] += e*whi.z; acc[7] += e*whi.w;
        }
    }
    #pragma unroll
    for (int h = 0; h < HH; h++)
        #pragma unroll
        for (int o = 16; o > 0; o >>= 1)
            acc[h] += __shfl_xor_sync(~0u, acc[h], o);

    if (lane < HH){
        float z = acc[lane];
        float sg  = 1.f / (1.f + expf(-5.f * z)) + 1e-5f;
        float sig = exp2f(sg * 1.5849625007211562f) - 1.f;   // 3^sg - 1
        int bb = row >> 9, t = row & 511;
        g_sigma[(bb*HH + lane)*TT + t] = sig;
    }
}

// ---------------------------------------------------------------------------
// bf16 NT GEMM for QKV (proven r12): BK=64, HROW=144, 3-stage cp.async.
// ---------------------------------------------------------------------------
__global__ void __launch_bounds__(256,2)
bf16_gemm_qkv(const __nv_bfloat16* __restrict__ A,
              const __nv_bfloat16* __restrict__ Bw,
              __nv_bfloat16* __restrict__ Cq, __nv_bfloat16* __restrict__ Ck,
              float* __restrict__ Cv)
{
    constexpr int HROW = 144;
    constexpr int STG  = 128*HROW;

    extern __shared__ float dsm[];
    const unsigned sb = (unsigned)__cvta_generic_to_shared(dsm);
    const unsigned aS = sb;
    const unsigned bS = sb + 3*STG;

    const int tid  = threadIdx.x;
    const int lane = tid & 31;
    const int wid  = tid >> 5;
    const int wm   = wid & 1;
    const int wn   = wid >> 1;
    const int g    = lane >> 2;
    const int t    = lane & 3;

    const int m0 = blockIdx.y * 128;
    const int n0 = blockIdx.x * 128;

    auto issue = [&](int st, int k0){
        unsigned ab = aS + st*STG, bb = bS + st*STG;
        #pragma unroll
        for (int e = 0; e < 4; e++){
            int idx2 = tid + 256*e;
            int r = idx2 >> 3, c8 = idx2 & 7;
            cp16(ab + (unsigned)(r*HROW + c8*16), A  + (long)(m0 + r)*512 + k0 + c8*8);
            cp16(bb + (unsigned)(r*HROW + c8*16), Bw + (long)(n0 + r)*512 + k0 + c8*8);
        }
    };

    const int arow = (lane & 7) + ((lane >> 3) & 1) * 8;
    const unsigned aFh = (unsigned)((wm*64 + arow)*HROW + (lane >> 4)*16);
    const unsigned bFh = (unsigned)((wn*32 + (lane & 7) + ((lane >> 4) & 1)*8)*HROW
                                    + ((lane >> 3) & 1)*16);

    float acc[4][4][4];
    #pragma unroll
    for (int i = 0; i < 4; i++)
        #pragma unroll
        for (int j = 0; j < 4; j++)
            #pragma unroll
            for (int p = 0; p < 4; p++) acc[i][j][p] = 0.f;

    issue(0, 0);  CPCOMMIT();
    issue(1, 64); CPCOMMIT();

    int buf = 0;
    for (int k0 = 0; k0 < 512; k0 += 64) {
        CPWAIT(1);
        __syncthreads();
        if (k0 + 128 < 512) {
            int nb = buf + 2; if (nb >= 3) nb -= 3;
            issue(nb, k0 + 128);
        }
        CPCOMMIT();

        const unsigned ab = aS + buf*STG;
        const unsigned bb = bS + buf*STG;

        uint4 bfr[2][4];
        #pragma unroll
        for (int ntp = 0; ntp < 2; ntp++)
            #pragma unroll
            for (int ks = 0; ks < 4; ks++)
                bfr[ntp][ks] = ldmx4(bb + bFh + (unsigned)(ntp*16*HROW + ks*32));

        #pragma unroll
        for (int ks = 0; ks < 4; ks++){
            #pragma unroll
            for (int mt = 0; mt < 4; mt++){
                uint4 a = ldmx4(ab + aFh + (unsigned)(mt*16*HROW + ks*32));
                #pragma unroll
                for (int ntp = 0; ntp < 2; ntp++){
                    mma16bf(acc[mt][2*ntp],   a.x, a.y, a.z, a.w,
                            bfr[ntp][ks].x, bfr[ntp][ks].y);
                    mma16bf(acc[mt][2*ntp+1], a.x, a.y, a.z, a.w,
                            bfr[ntp][ks].z, bfr[ntp][ks].w);
                }
            }
        }
        buf++; if (buf == 3) buf = 0;
    }

    #pragma unroll
    for (int mt = 0; mt < 4; mt++){
        #pragma unroll
        for (int nt = 0; nt < 4; nt++){
            int row = m0 + wm*64 + mt*16 + g;
            int col = n0 + wn*32 + nt*8 + 2*t;
            float v0 = acc[mt][nt][0], v1 = acc[mt][nt][1];
            float v2 = acc[mt][nt][2], v3 = acc[mt][nt][3];
            if (n0 < 512){
                __nv_bfloat162 h0, h1;
                h0.x = __float2bfloat16(v0); h0.y = __float2bfloat16(v1);
                h1.x = __float2bfloat16(v2); h1.y = __float2bfloat16(v3);
                *(__nv_bfloat162*)&Cq[(long)row*512 + col]     = h0;
                *(__nv_bfloat162*)&Cq[(long)(row+8)*512 + col] = h1;
            } else if (n0 < 1024){
                int c2 = col - 512;
                __nv_bfloat162 h0, h1;
                h0.x = __float2bfloat16(v0); h0.y = __float2bfloat16(v1);
                h1.x = __float2bfloat16(v2); h1.y = __float2bfloat16(v3);
                *(__nv_bfloat162*)&Ck[(long)row*512 + c2]     = h0;
                *(__nv_bfloat162*)&Ck[(long)(row+8)*512 + c2] = h1;
            } else {
                int vc = col - 1024;
                long base0 = (long)(row >> 9) * (512L*512) + (row & 511);
                Cv[base0 + (long)vc*512]         = tf32r(v0);
                Cv[base0 + (long)(vc+1)*512]     = tf32r(v1);
                Cv[base0 + 8 + (long)vc*512]     = tf32r(v2);
                Cv[base0 + 8 + (long)(vc+1)*512] = tf32r(v3);
            }
        }
    }
}

// ---------------------------------------------------------------------------
// tf32 NT GEMM (out-proj, proven r12): C = A@B^T + bias + res.  BK=32.
// ---------------------------------------------------------------------------
__global__ void __launch_bounds__(256,2)
tf32_gemm_out(const float* __restrict__ A, const float* __restrict__ Bw,
              float* __restrict__ C,
              const float* __restrict__ bias, const float* __restrict__ res)
{
    constexpr int ST  = 36;
    constexpr int STG = 128*ST*4;

    extern __shared__ float dsm[];
    const unsigned sb = (unsigned)__cvta_generic_to_shared(dsm);
    const unsigned aS = sb;
    const unsigned bS = sb + 3*STG;

    const int tid  = threadIdx.x;
    const int lane = tid & 31;
    const int wid  = tid >> 5;
    const int wm   = wid & 1;
    const int wn   = wid >> 1;
    const int g    = lane >> 2;
    const int t    = lane & 3;

    const int m0 = blockIdx.y * 128;
    const int n0 = blockIdx.x * 128;

    const int rl = tid >> 3;
    const int qc = tid & 7;

    const float* Ag = A  + (long)(m0 + rl) * 512 + qc*4;
    const float* Bg = Bw + (long)(n0 + rl) * 512 + qc*4;
    const unsigned dA = (unsigned)(rl*ST + qc*4) * 4;

    auto issue = [&](int st, int k0){
        unsigned ab = aS + st*STG, bb = bS + st*STG;
        #pragma unroll
        for (int e = 0; e < 4; e++){
            cp16(ab + dA + e*32*ST*4, Ag + (long)e*32*512 + k0);
            cp16(bb + dA + e*32*ST*4, Bg + (long)e*32*512 + k0);
        }
    };

    const int arow = (lane & 7) + ((lane >> 3) & 1) * 8;
    const int acol = (lane >> 4) * 4;
    const unsigned aFB = (unsigned)((wm*64 + arow)*ST + acol) * 4;
    const unsigned bFB = (unsigned)((wn*32 + (lane & 7))*ST + (lane >> 3)*4) * 4;

    float acc[4][4][4];
    #pragma unroll
    for (int i = 0; i < 4; i++)
        #pragma unroll
        for (int j = 0; j < 4; j++)
            #pragma unroll
            for (int p = 0; p < 4; p++) acc[i][j][p] = 0.f;

    issue(0, 0);  CPCOMMIT();
    issue(1, 32); CPCOMMIT();

    int buf = 0;
    for (int k0 = 0; k0 < 512; k0 += 32) {
        CPWAIT(1);
        __syncthreads();
        if (k0 + 64 < 512) {
            int nb = buf + 2; if (nb >= 3) nb -= 3;
            issue(nb, k0 + 64);
        }
        CPCOMMIT();

        const unsigned ab = aS + buf*STG;
        const unsigned bb = bS + buf*STG;

        uint4 bfr[4][2];
        #pragma unroll
        for (int nt = 0; nt < 4; nt++)
            #pragma unroll
            for (int kg = 0; kg < 2; kg++)
                bfr[nt][kg] = ldmx4(bb + bFB + (unsigned)(nt*8*ST + kg*16)*4);

        #pragma unroll
        for (int ks = 0; ks < 4; ks++) {
            #pragma unroll
            for (int mt = 0; mt < 4; mt++) {
                uint4 a = ldmx4(ab + aFB + (unsigned)(mt*16*ST + ks*8)*4);
                #pragma unroll
                for (int nt = 0; nt < 4; nt++)
                    mma8(acc[mt][nt], a.x, a.y, a.z, a.w,
                         (ks & 1) ? bfr[nt][ks>>1].z : bfr[nt][ks>>1].x,
                         (ks & 1) ? bfr[nt][ks>>1].w : bfr[nt][ks>>1].y);
            }
        }
        buf++; if (buf == 3) buf = 0;
    }

    #pragma unroll
    for (int mt = 0; mt < 4; mt++){
        #pragma unroll
        for (int nt = 0; nt < 4; nt++){
            int row = m0 + wm*64 + mt*16 + g;
            int col = n0 + wn*32 + nt*8 + 2*t;
            float v0 = acc[mt][nt][0] + bias[col]   + res[(long)row*512 + col];
            float v1 = acc[mt][nt][1] + bias[col+1] + res[(long)row*512 + col+1];
            float v2 = acc[mt][nt][2] + bias[col]   + res[(long)(row+8)*512 + col];
            float v3 = acc[mt][nt][3] + bias[col+1] + res[(long)(row+8)*512 + col+1];
            *(float2*)&C[(long)row*512 + col]     = make_float2(v0, v1);
            *(float2*)&C[(long)(row+8)*512 + col] = make_float2(v2, v3);
        }
    }
}

// ---------------------------------------------------------------------------
// MEGA kernel: attention (bf16 QK + tf32 AV) + prior + style (proven r12).
// ---------------------------------------------------------------------------
__global__ void __launch_bounds__(256,2)
mega_attn_kernel(const __nv_bfloat16* __restrict__ Q,
                 const __nv_bfloat16* __restrict__ Kt,
                 const float* __restrict__ Vt,
                 float* __restrict__ S, float* __restrict__ Y,
                 float* __restrict__ prior, float* __restrict__ sfull,
                 const float* __restrict__ emb,
                 const float* __restrict__ embW,
                 const float* __restrict__ embB)
{
    extern __shared__ float dsm[];
    const int tid  = threadIdx.x;
    const unsigned bx = blockIdx.x;

    // ---------------- style blocks ----------------
    if (bx >= 8192){
        int sb = bx - 8192;
        int bb = sb >> 2, part = sb & 3;
        float* se = dsm;
        for (int i = tid; i < TEDIM; i += 256){
            float e = emb[(size_t)bb * TEDIM + i];
            se[i] = siluf(e);
        }
        __syncthreads();
        int j = part*256 + tid;
        float acc = 0.f;
        for (int k = 0; k < TEDIM; k++)
            acc += se[k] * embW[(size_t)k * (2*DDIM) + j];
        g_style[bb * (2*DDIM) + j] = acc + embB[j];
        return;
    }

    // ---------------- prior blocks ----------------
    if (bx & 1){
        long base = (long)(bx >> 1) * 32;
        int w = tid >> 5, l = tid & 31;
        #pragma unroll
        for (int i = 0; i < 4; i++){
            long row = base + w*4 + i;
            int n = (int)(row & 511);
            float s = g_sigma[row];
            float inv2 = -1.f / (2.f * s * s);
            float coef = 0.3989422804014327f / s;
            float4 sv = make_float4(s, s, s, s);
            float4* pp = (float4*)(prior + row * TT);
            float4* sp = (float4*)(sfull + row * TT);
            #pragma unroll
            for (int j = 0; j < 4; j++){
                int c4 = l + j*32;
                int m = c4 * 4;
                float d0 = (float)(n - m);
                float d1 = (float)(n - (m+1));
                float d2 = (float)(n - (m+2));
                float d3 = (float)(n - (m+3));
                float4 pv;
                pv.x = __expf(d0*d0*inv2) * coef;
                pv.y = __expf(d1*d1*inv2) * coef;
                pv.z = __expf(d2*d2*inv2) * coef;
                pv.w = __expf(d3*d3*inv2) * coef;
                pp[c4] = pv;
                sp[c4] = sv;
            }
        }
        return;
    }

    // ---------------- attention blocks ----------------
    const int idx = bx >> 1;
    const int bh = idx >> 4;          // b*8+h
    const int m0 = (idx & 15) * 32;

    constexpr int VST = 132;
    constexpr int SST = 132;
    constexpr int HROW = 144;
    const unsigned A_BYTES = 8704;
    const unsigned B_BYTES = 34816;

    const unsigned sb  = (unsigned)__cvta_generic_to_shared(dsm);
    const unsigned sbA = sb;
    const unsigned sbB = sb + A_BYTES;
    const unsigned sbS = sb + A_BYTES + 2*B_BYTES;
    float* red = dsm + (A_BYTES + 2*B_BYTES)/4 + 32*SST;

    const int lane = tid & 31;
    const int wid  = tid >> 5;
    const int wm   = wid & 1;
    const int wn   = wid >> 1;
    const int g    = lane >> 2;
    const int t    = lane & 3;

    const int b  = bh >> 3, h = bh & 7;

    const __nv_bfloat16* Qb = Q + ((long)b*512 + m0)*512 + h*64;
    const __nv_bfloat16* Kb = Kt + ((long)b*512)*512 + h*64;
    const float* Vb = Vt + (long)b*(512L*512) + (long)h*64*512;
    float* Sb = S + ((long)bh*512 + m0)*512;
    float* Yb = Y + ((long)b*512)*512 + h*64;

    const int arow = (lane & 7) + ((lane >> 3) & 1) * 8;
    const unsigned aFh = sbA + (unsigned)((wm*16 + arow)*HROW + (lane >> 4)*16);
    const unsigned bFh0 = (unsigned)((wn*32 + (lane & 7) + ((lane >> 4) & 1)*8)*HROW
                                     + ((lane >> 3) & 1)*16);
    const unsigned bFh1 = bFh0 + (unsigned)(16*HROW);

    const unsigned sF  = sbS + (unsigned)((wm*16 + arow)*SST + (lane >> 4)*4) * 4;
    const unsigned vF  = (unsigned)((wn*16 + (lane & 7))*VST + (lane >> 3)*4) * 4;

    auto issueB = [&](int chunk, int bufb){
        unsigned dst = sbB + (unsigned)bufb * B_BYTES;
        const __nv_bfloat16* src = Kb + (long)(chunk*128)*512;
        #pragma unroll
        for (int e = 0; e < 4; e++){
            int idx2 = tid + 256*e;
            int r = idx2 >> 3, c8 = idx2 & 7;
            cp16(dst + (unsigned)(r*HROW + c8*16), src + (long)r*512 + c8*8);
        }
    };
    auto issueV = [&](int chunk, int bufb){
        unsigned dst = sbB + (unsigned)bufb * B_BYTES;
        #pragma unroll
        for (int e = 0; e < 8; e++){
            int idx2 = tid + 256*e;
            int r  = idx2 >> 5;
            int qc = idx2 & 31;
            cp16(dst + (unsigned)(r*VST + qc*4)*4,
                 Vb + (long)r*512 + chunk*128 + qc*4);
        }
    };

    // group 0: Q tile (bf16) + K chunk 0
    {
        int r = tid >> 3, c8 = tid & 7;
        cp16(sbA + (unsigned)(r*HROW + c8*16), Qb + (long)r*512 + c8*8);
        issueB(0, 0);
        CPCOMMIT();
    }

    float acc[4][4][4];
    #pragma unroll
    for (int c = 0; c < 4; c++)
        #pragma unroll
        for (int nt = 0; nt < 4; nt++)
            #pragma unroll
            for (int p = 0; p < 4; p++) acc[c][nt][p] = 0.f;

    for (int c = 0; c < 4; c++){
        CPWAIT(0);
        __syncthreads();
        if (c + 1 < 4) issueB(c + 1, (c + 1) & 1);
        CPCOMMIT();

        const unsigned bb2 = sbB + (unsigned)(c & 1) * B_BYTES;
        #pragma unroll
        for (int ks = 0; ks < 4; ks++){
            uint4 a = ldmx4(aFh + (unsigned)(ks*32));
            uint4 bv0 = ldmx4(bb2 + bFh0 + (unsigned)(ks*32));
            mma16bf(acc[c][0], a.x, a.y, a.z, a.w, bv0.x, bv0.y);
            mma16bf(acc[c][1], a.x, a.y, a.z, a.w, bv0.z, bv0.w);
            uint4 bv1 = ldmx4(bb2 + bFh1 + (unsigned)(ks*32));
            mma16bf(acc[c][2], a.x, a.y, a.z, a.w, bv1.x, bv1.y);
            mma16bf(acc[c][3], a.x, a.y, a.z, a.w, bv1.z, bv1.w);
        }
    }
    __syncthreads();                      // protect V prefetch overwriting buf 1

    issueV(0, 0); CPCOMMIT();
    issueV(1, 1); CPCOMMIT();

    #pragma unroll
    for (int c = 0; c < 4; c++)
        #pragma unroll
        for (int nt = 0; nt < 4; nt++)
            #pragma unroll
            for (int p = 0; p < 4; p++) acc[c][nt][p] *= (1.f/64.f);

    const int r0 = wm*16 + g, r1 = r0 + 8;

    float mx0 = -1e30f, mx1 = -1e30f;
    #pragma unroll
    for (int c = 0; c < 4; c++)
        #pragma unroll
        for (int nt = 0; nt < 4; nt++){
            mx0 = fmaxf(mx0, fmaxf(acc[c][nt][0], acc[c][nt][1]));
            mx1 = fmaxf(mx1, fmaxf(acc[c][nt][2], acc[c][nt][3]));
        }
    #pragma unroll
    for (int o = 1; o <= 2; o <<= 1){
        mx0 = fmaxf(mx0, __shfl_xor_sync(~0u, mx0, o));
        mx1 = fmaxf(mx1, __shfl_xor_sync(~0u, mx1, o));
    }
    if (t == 0){ red[r0*4 + wn] = mx0; red[r1*4 + wn] = mx1; }
    __syncthreads();
    float rm0 = fmaxf(fmaxf(red[r0*4+0], red[r0*4+1]), fmaxf(red[r0*4+2], red[r0*4+3]));
    float rm1 = fmaxf(fmaxf(red[r1*4+0], red[r1*4+1]), fmaxf(red[r1*4+2], red[r1*4+3]));
    __syncthreads();

    float s0 = 0.f, s1 = 0.f;
    #pragma unroll
    for (int c = 0; c < 4; c++)
        #pragma unroll
        for (int nt = 0; nt < 4; nt++){
            acc[c][nt][0] = __expf(acc[c][nt][0] - rm0);
            acc[c][nt][1] = __expf(acc[c][nt][1] - rm0);
            acc[c][nt][2] = __expf(acc[c][nt][2] - rm1);
            acc[c][nt][3] = __expf(acc[c][nt][3] - rm1);
            s0 += acc[c][nt][0] + acc[c][nt][1];
            s1 += acc[c][nt][2] + acc[c][nt][3];
        }
    #pragma unroll
    for (int o = 1; o <= 2; o <<= 1){
        s0 += __shfl_xor_sync(~0u, s0, o);
        s1 += __shfl_xor_sync(~0u, s1, o);
    }
    if (t == 0){ red[r0*4 + wn] = s0; red[r1*4 + wn] = s1; }
    __syncthreads();
    float inv0 = 1.f / (red[r0*4+0] + red[r0*4+1] + red[r0*4+2] + red[r0*4+3]);
    float inv1 = 1.f / (red[r1*4+0] + red[r1*4+1] + red[r1*4+2] + red[r1*4+3]);

    float yacc[2][4];
    #pragma unroll
    for (int nt = 0; nt < 2; nt++)
        #pragma unroll
        for (int p = 0; p < 4; p++) yacc[nt][p] = 0.f;

    float* Srow0 = dsm + (A_BYTES + 2*B_BYTES)/4;
    float* p0 = Sb + (long)r0*512;
    float* p1 = Sb + (long)r1*512;

    #pragma unroll
    for (int c = 0; c < 4; c++){
        #pragma unroll
        for (int nt = 0; nt < 4; nt++){
            int colc = wn*32 + nt*8 + 2*t;
            float n00 = acc[c][nt][0]*inv0, n01 = acc[c][nt][1]*inv0;
            float n10 = acc[c][nt][2]*inv1, n11 = acc[c][nt][3]*inv1;
            Srow0[r0*SST + colc]   = tf32r(n00);
            Srow0[r0*SST + colc+1] = tf32r(n01);
            Srow0[r1*SST + colc]   = tf32r(n10);
            Srow0[r1*SST + colc+1] = tf32r(n11);
            *(float2*)&p0[c*128 + colc] = make_float2(n00, n01);
            *(float2*)&p1[c*128 + colc] = make_float2(n10, n11);
        }
        if (c < 3) { CPWAIT(1); } else { CPWAIT(0); }
        __syncthreads();

        const unsigned vb = sbB + (unsigned)(c & 1) * B_BYTES;
        #pragma unroll
        for (int kg = 0; kg < 8; kg++){
            uint4 a0 = ldmx4(sF + (unsigned)(kg*16 + 0)*4);
            uint4 a1 = ldmx4(sF + (unsigned)(kg*16 + 8)*4);
            #pragma unroll
            for (int nt = 0; nt < 2; nt++){
                uint4 bv = ldmx4(vb + vF + (unsigned)(nt*8*VST + kg*16)*4);
                mma8(yacc[nt], a0.x, a0.y, a0.z, a0.w, bv.x, bv.y);
                mma8(yacc[nt], a1.x, a1.y, a1.z, a1.w, bv.z, bv.w);
            }
        }
        __syncthreads();
        if (c + 2 < 4){ issueV(c + 2, c & 1); }
        CPCOMMIT();
    }

    #pragma unroll
    for (int nt = 0; nt < 2; nt++){
        int col = wn*16 + nt*8 + 2*t;
        int rowA = m0 + r0, rowB = m0 + r1;
        *(float2*)&Yb[(long)rowA*512 + col] = make_float2(yacc[nt][0], yacc[nt][1]);
        *(float2*)&Yb[(long)rowB*512 + col] = make_float2(yacc[nt][2], yacc[nt][3]);
    }
}

// ---------------------------------------------------------------------------
// LN2 + scale/shift + silu, WARP-PER-ROW (8 rows/block, no barriers).
// hs stored tf32-rounded fp32 (feeds tf32 out-proj).
// ---------------------------------------------------------------------------
__global__ void __launch_bounds__(256)
ln2_style_kernel(const float* __restrict__ g,
                 const float* __restrict__ b)
{
    const int tid  = threadIdx.x;
    const int warp = tid >> 5, lane = tid & 31;
    const int row  = blockIdx.x * 8 + warp;
    const int bb   = row >> 9;

    const float4* yr = (const float4*)(g_y + (size_t)row * DDIM);
    float4 v[4];
    float s = 0.f, sq = 0.f;
    #pragma unroll
    for (int i = 0; i < 4; i++){
        v[i] = yr[lane + 32*i];
        s  += v[i].x + v[i].y + v[i].z + v[i].w;
        sq += v[i].x*v[i].x + v[i].y*v[i].y + v[i].z*v[i].z + v[i].w*v[i].w;
    }
    #pragma unroll
    for (int o = 16; o > 0; o >>= 1){
        s  += __shfl_xor_sync(~0u, s,  o);
        sq += __shfl_xor_sync(~0u, sq, o);
    }
    float mean = s * (1.f / DDIM);
    float var  = sq * (1.f / DDIM) - mean * mean;
    float rstd = rsqrtf(var + 1e-5f);

    const float4* sc = (const float4*)(g_style + bb * (2*DDIM));
    const float4* sh = (const float4*)(g_style + bb * (2*DDIM) + DDIM);
    float4* hw = (float4*)(g_hs + (size_t)row * DDIM);

    #pragma unroll
    for (int i = 0; i < 4; i++){
        int q = lane + 32*i;
        float4 g4 = ((const float4*)g)[q];
        float4 b4 = ((const float4*)b)[q];
        float4 s4 = sc[q];
        float4 f4 = sh[q];
        float n0 = (v[i].x - mean)*rstd*g4.x + b4.x;
        float n1 = (v[i].y - mean)*rstd*g4.y + b4.y;
        float n2 = (v[i].z - mean)*rstd*g4.z + b4.z;
        float n3 = (v[i].w - mean)*rstd*g4.w + b4.w;
        float4 o4;
        o4.x = tf32r(siluf(n0*(1.f + s4.x) + f4.x));
        o4.y = tf32r(siluf(n1*(1.f + s4.y) + f4.y));
        o4.z = tf32r(siluf(n2*(1.f + s4.z) + f4.z));
        o4.w = tf32r(siluf(n3*(1.f + s4.w) + f4.w));
        hw[q] = o4;
    }
}

// ---------------------------------------------------------------------------
extern "C" void kernel_launch(void* const* d_in, const int* in_sizes, int n_in,
                              void* d_out, int out_size)
{
    const float* x    = (const float*)d_in[0];
    const float* emb  = (const float*)d_in[1];
    const float* Wq   = (const float*)d_in[2];
    const float* Wk   = (const float*)d_in[3];
    const float* Wv   = (const float*)d_in[4];
    const float* Wsig = (const float*)d_in[5];
    const float* ln1g = (const float*)d_in[6];
    const float* ln1b = (const float*)d_in[7];
    const float* embW = (const float*)d_in[8];
    const float* embB = (const float*)d_in[9];
    const float* ln2g = (const float*)d_in[10];
    const float* ln2b = (const float*)d_in[11];
    const float* outW = (const float*)d_in[12];
    const float* outB = (const float*)d_in[13];

    float* out    = (float*)d_out;
    float* outY   = out;
    float* outS   = out + YN;
    float* outP   = outS + SN;
    float* outSig = outP + SN;

    float *pv, *py, *phs, *pwr;
    __nv_bfloat16 *pxnh, *pqh, *pkh, *pwh;
    cudaGetSymbolAddress((void**)&pxnh, g_xnh);
    cudaGetSymbolAddress((void**)&pqh, g_qh);
    cudaGetSymbolAddress((void**)&pkh, g_kh);
    cudaGetSymbolAddress((void**)&pwh, g_wh);
    cudaGetSymbolAddress((void**)&pv,  g_v);
    cudaGetSymbolAddress((void**)&py,  g_y);
    cudaGetSymbolAddress((void**)&phs, g_hs);
    cudaGetSymbolAddress((void**)&pwr, g_wr);

    const int SMG = 3*2*128*36*4;                            // 110592
    const int SMH = 3*2*128*144;                             // 110592
    const int SMF = 8704 + 2*34816 + 32*132*4 + 512;         // 95744

    cudaFuncSetAttribute(bf16_gemm_qkv,     cudaFuncAttributeMaxDynamicSharedMemorySize, SMH);
    cudaFuncSetAttribute(tf32_gemm_out,     cudaFuncAttributeMaxDynamicSharedMemorySize, SMG);
    cudaFuncSetAttribute(mega_attn_kernel,  cudaFuncAttributeMaxDynamicSharedMemorySize, SMF);

    // 1) LN1 + sigma (warp-per-row) + weight conversion (packed)
    ln1_sigma_roundw_kernel<<<2048 + WSZ/256, 256>>>(
        x, ln1g, ln1b, Wsig, Wq, Wk, Wv, outW);

    // 2) merged QKV projection in bf16 (Q/K -> bf16, V -> tf32 transposed)
    bf16_gemm_qkv<<<dim3(12, MROWS/128), 256, SMH>>>(
        pxnh, pwh, pqh, pkh, pv);

    // 3) MEGA: attention (bf16 QK + tf32 AV) + prior + sigma_full + style
    mega_attn_kernel<<<8192 + 128, 256, SMF>>>(
        pqh, pkh, pv, outS, py, outP, outSig, emb, embW, embB);

    // 4) LN2 + style + silu (warp-per-row, tf32 hs)
    ln2_style_kernel<<<2048, 256>>>(ln2g, ln2b);

    // 5) y_out = x + silu_h @ out_W^T + out_b  (tf32 GEMM, proven)
    tf32_gemm_out<<<dim3(4, MROWS/128), 256, SMG>>>(
        phs, pwr, outY, outB, x);
}

// round 16
// speedup vs baseline: 1.3490x; 1.0331x over previous
#include <cuda_runtime.h>
#include <cuda_bf16.h>

// Problem constants
#define BQ   32
#define TT   512
#define DDIM 512
#define HH   8
#define HD   64
#define TEDIM 2048
#define MROWS (BQ*TT)            // 16384
#define YN ((size_t)BQ*TT*DDIM)  // 8388608
#define SN ((size_t)BQ*HH*TT*TT) // 67108864
#define WSZ (DDIM*DDIM)          // 262144

// Scratch (device globals — no allocation allowed)
__device__ __nv_bfloat16 g_xnh[BQ*TT*DDIM];  // LN1 output, bf16
__device__ __nv_bfloat16 g_qh[BQ*TT*DDIM];   // Q in bf16
__device__ __nv_bfloat16 g_kh[BQ*TT*DDIM];   // K in bf16
__device__ float g_v [BQ*TT*DDIM];   // stored TRANSPOSED: [b][h*64+d][t] (tf32)
__device__ float g_y [BQ*TT*DDIM];
__device__ float g_hs[BQ*TT*DDIM];   // LN2/silu output, tf32-rounded fp32
__device__ float g_sigma[BQ*HH*TT];
__device__ float g_style[BQ*2*DDIM];
__device__ __nv_bfloat16 g_wh[3*WSZ];        // bf16 [Wq;Wk;Wv] (1536x512)
__device__ float g_wr[WSZ];                  // tf32-rounded outW

__device__ __forceinline__ float siluf(float z){ return z / (1.f + expf(-z)); }

__device__ __forceinline__ float tf32r(float f){
    unsigned u; asm("cvt.rna.tf32.f32 %0, %1;" : "=r"(u) : "f"(f));
    return __uint_as_float(u);
}

__device__ __forceinline__ void mma8(float* c,
    unsigned a0, unsigned a1, unsigned a2, unsigned a3,
    unsigned b0, unsigned b1)
{
    asm volatile(
        "mma.sync.aligned.m16n8k8.row.col.f32.tf32.tf32.f32 "
        "{%0,%1,%2,%3}, {%4,%5,%6,%7}, {%8,%9}, {%0,%1,%2,%3};"
        : "+f"(c[0]), "+f"(c[1]), "+f"(c[2]), "+f"(c[3])
        : "r"(a0), "r"(a1), "r"(a2), "r"(a3), "r"(b0), "r"(b1));
}

__device__ __forceinline__ void mma16bf(float* c,
    unsigned a0, unsigned a1, unsigned a2, unsigned a3,
    unsigned b0, unsigned b1)
{
    asm volatile(
        "mma.sync.aligned.m16n8k16.row.col.f32.bf16.bf16.f32 "
        "{%0,%1,%2,%3}, {%4,%5,%6,%7}, {%8,%9}, {%0,%1,%2,%3};"
        : "+f"(c[0]), "+f"(c[1]), "+f"(c[2]), "+f"(c[3])
        : "r"(a0), "r"(a1), "r"(a2), "r"(a3), "r"(b0), "r"(b1));
}

__device__ __forceinline__ void cp16(unsigned dst, const void* src){
    asm volatile("cp.async.cg.shared.global [%0], [%1], 16;" :: "r"(dst), "l"(src));
}
#define CPCOMMIT() asm volatile("cp.async.commit_group;" ::: "memory")
#define CPWAIT(n)  asm volatile("cp.async.wait_group %0;" :: "n"(n) : "memory")

__device__ __forceinline__ uint4 ldmx4(unsigned a){
    uint4 r;
    asm volatile("ldmatrix.sync.aligned.m8n8.x4.shared.b16 {%0,%1,%2,%3}, [%4];"
        : "=r"(r.x), "=r"(r.y), "=r"(r.z), "=r"(r.w) : "r"(a));
    return r;
}

// ---------------------------------------------------------------------------
// LN1 + sigma, WARP-PER-ROW (proven r14), plus weight conversion packed in.
// ---------------------------------------------------------------------------
__global__ void __launch_bounds__(256)
ln1_sigma_roundw_kernel(const float* __restrict__ x,
                        const float* __restrict__ g,
                        const float* __restrict__ b,
                        const float* __restrict__ Wsig,
                        const float* __restrict__ w0,
                        const float* __restrict__ w1,
                        const float* __restrict__ w2,
                        const float* __restrict__ w3)
{
    int tid = threadIdx.x;
    if (blockIdx.x >= 2048){
        int i = (blockIdx.x - 2048) * 256 + tid;
        g_wh[i]         = __float2bfloat16(w0[i]);
        g_wh[i +   WSZ] = __float2bfloat16(w1[i]);
        g_wh[i + 2*WSZ] = __float2bfloat16(w2[i]);
        g_wr[i]         = tf32r(w3[i]);
        return;
    }
    const int warp = tid >> 5, lane = tid & 31;
    const int row  = blockIdx.x * 8 + warp;
    const float4* xr = (const float4*)(x + (size_t)row * DDIM);

    float4 v[4];
    float s = 0.f, sq = 0.f;
    #pragma unroll
    for (int i = 0; i < 4; i++){
        v[i] = xr[lane + 32*i];
        s  += v[i].x + v[i].y + v[i].z + v[i].w;
        sq += v[i].x*v[i].x + v[i].y*v[i].y + v[i].z*v[i].z + v[i].w*v[i].w;
    }
    #pragma unroll
    for (int o = 16; o > 0; o >>= 1){
        s  += __shfl_xor_sync(~0u, s,  o);
        sq += __shfl_xor_sync(~0u, sq, o);
    }
    float mean = s * (1.f / DDIM);
    float var  = sq * (1.f / DDIM) - mean * mean;
    float rstd = rsqrtf(var + 1e-5f);

    float acc[HH];
    #pragma unroll
    for (int h = 0; h < HH; h++) acc[h] = 0.f;

    #pragma unroll
    for (int i = 0; i < 4; i++){
        int c = (lane + 32*i) * 4;
        float4 g4 = ((const float4*)g)[lane + 32*i];
        float4 b4 = ((const float4*)b)[lane + 32*i];
        float n0 = (v[i].x - mean)*rstd*g4.x + b4.x;
        float n1 = (v[i].y - mean)*rstd*g4.y + b4.y;
        float n2 = (v[i].z - mean)*rstd*g4.z + b4.z;
        float n3 = (v[i].w - mean)*rstd*g4.w + b4.w;
        __nv_bfloat162 h01, h23;
        h01.x = __float2bfloat16(n0); h01.y = __float2bfloat16(n1);
        h23.x = __float2bfloat16(n2); h23.y = __float2bfloat16(n3);
        *(__nv_bfloat162*)&g_xnh[(size_t)row*DDIM + c]     = h01;
        *(__nv_bfloat162*)&g_xnh[(size_t)row*DDIM + c + 2] = h23;

        const float* el = (const float*)&v[i];
        #pragma unroll
        for (int j = 0; j < 4; j++){
            float4 wlo = ((const float4*)Wsig)[(c + j)*2];
            float4 whi = ((const float4*)Wsig)[(c + j)*2 + 1];
            float e = el[j];
            acc[0] += e*wlo.x; acc[1] += e*wlo.y; acc[2] += e*wlo.z; acc[3] += e*wlo.w;
            acc[4] += e*whi.x; acc[5] += e*whi.y; acc[6] += e*whi.z; acc[7] += e*whi.w;
        }
    }
    #pragma unroll
    for (int h = 0; h < HH; h++)
        #pragma unroll
        for (int o = 16; o > 0; o >>= 1)
            acc[h] += __shfl_xor_sync(~0u, acc[h], o);

    if (lane < HH){
        float z = acc[lane];
        float sg  = 1.f / (1.f + expf(-5.f * z)) + 1e-5f;
        float sig = exp2f(sg * 1.5849625007211562f) - 1.f;   // 3^sg - 1
        int bb = row >> 9, t = row & 511;
        g_sigma[(bb*HH + lane)*TT + t] = sig;
    }
}

// ---------------------------------------------------------------------------
// bf16 NT GEMM for QKV (proven r12): BK=64, HROW=144, 3-stage cp.async.
// ---------------------------------------------------------------------------
__global__ void __launch_bounds__(256,2)
bf16_gemm_qkv(const __nv_bfloat16* __restrict__ A,
              const __nv_bfloat16* __restrict__ Bw,
              __nv_bfloat16* __restrict__ Cq, __nv_bfloat16* __restrict__ Ck,
              float* __restrict__ Cv)
{
    constexpr int HROW = 144;
    constexpr int STG  = 128*HROW;

    extern __shared__ float dsm[];
    const unsigned sb = (unsigned)__cvta_generic_to_shared(dsm);
    const unsigned aS = sb;
    const unsigned bS = sb + 3*STG;

    const int tid  = threadIdx.x;
    const int lane = tid & 31;
    const int wid  = tid >> 5;
    const int wm   = wid & 1;
    const int wn   = wid >> 1;
    const int g    = lane >> 2;
    const int t    = lane & 3;

    const int m0 = blockIdx.y * 128;
    const int n0 = blockIdx.x * 128;

    auto issue = [&](int st, int k0){
        unsigned ab = aS + st*STG, bb = bS + st*STG;
        #pragma unroll
        for (int e = 0; e < 4; e++){
            int idx2 = tid + 256*e;
            int r = idx2 >> 3, c8 = idx2 & 7;
            cp16(ab + (unsigned)(r*HROW + c8*16), A  + (long)(m0 + r)*512 + k0 + c8*8);
            cp16(bb + (unsigned)(r*HROW + c8*16), Bw + (long)(n0 + r)*512 + k0 + c8*8);
        }
    };

    const int arow = (lane & 7) + ((lane >> 3) & 1) * 8;
    const unsigned aFh = (unsigned)((wm*64 + arow)*HROW + (lane >> 4)*16);
    const unsigned bFh = (unsigned)((wn*32 + (lane & 7) + ((lane >> 4) & 1)*8)*HROW
                                    + ((lane >> 3) & 1)*16);

    float acc[4][4][4];
    #pragma unroll
    for (int i = 0; i < 4; i++)
        #pragma unroll
        for (int j = 0; j < 4; j++)
            #pragma unroll
            for (int p = 0; p < 4; p++) acc[i][j][p] = 0.f;

    issue(0, 0);  CPCOMMIT();
    issue(1, 64); CPCOMMIT();

    int buf = 0;
    for (int k0 = 0; k0 < 512; k0 += 64) {
        CPWAIT(1);
        __syncthreads();
        if (k0 + 128 < 512) {
            int nb = buf + 2; if (nb >= 3) nb -= 3;
            issue(nb, k0 + 128);
        }
        CPCOMMIT();

        const unsigned ab = aS + buf*STG;
        const unsigned bb = bS + buf*STG;

        uint4 bfr[2][4];
        #pragma unroll
        for (int ntp = 0; ntp < 2; ntp++)
            #pragma unroll
            for (int ks = 0; ks < 4; ks++)
                bfr[ntp][ks] = ldmx4(bb + bFh + (unsigned)(ntp*16*HROW + ks*32));

        #pragma unroll
        for (int ks = 0; ks < 4; ks++){
            #pragma unroll
            for (int mt = 0; mt < 4; mt++){
                uint4 a = ldmx4(ab + aFh + (unsigned)(mt*16*HROW + ks*32));
                #pragma unroll
                for (int ntp = 0; ntp < 2; ntp++){
                    mma16bf(acc[mt][2*ntp],   a.x, a.y, a.z, a.w,
                            bfr[ntp][ks].x, bfr[ntp][ks].y);
                    mma16bf(acc[mt][2*ntp+1], a.x, a.y, a.z, a.w,
                            bfr[ntp][ks].z, bfr[ntp][ks].w);
                }
            }
        }
        buf++; if (buf == 3) buf = 0;
    }

    #pragma unroll
    for (int mt = 0; mt < 4; mt++){
        #pragma unroll
        for (int nt = 0; nt < 4; nt++){
            int row = m0 + wm*64 + mt*16 + g;
            int col = n0 + wn*32 + nt*8 + 2*t;
            float v0 = acc[mt][nt][0], v1 = acc[mt][nt][1];
            float v2 = acc[mt][nt][2], v3 = acc[mt][nt][3];
            if (n0 < 512){
                __nv_bfloat162 h0, h1;
                h0.x = __float2bfloat16(v0); h0.y = __float2bfloat16(v1);
                h1.x = __float2bfloat16(v2); h1.y = __float2bfloat16(v3);
                *(__nv_bfloat162*)&Cq[(long)row*512 + col]     = h0;
                *(__nv_bfloat162*)&Cq[(long)(row+8)*512 + col] = h1;
            } else if (n0 < 1024){
                int c2 = col - 512;
                __nv_bfloat162 h0, h1;
                h0.x = __float2bfloat16(v0); h0.y = __float2bfloat16(v1);
                h1.x = __float2bfloat16(v2); h1.y = __float2bfloat16(v3);
                *(__nv_bfloat162*)&Ck[(long)row*512 + c2]     = h0;
                *(__nv_bfloat162*)&Ck[(long)(row+8)*512 + c2] = h1;
            } else {
                int vc = col - 1024;
                long base0 = (long)(row >> 9) * (512L*512) + (row & 511);
                Cv[base0 + (long)vc*512]         = tf32r(v0);
                Cv[base0 + (long)(vc+1)*512]     = tf32r(v1);
                Cv[base0 + 8 + (long)vc*512]     = tf32r(v2);
                Cv[base0 + 8 + (long)(vc+1)*512] = tf32r(v3);
            }
        }
    }
}

// ---------------------------------------------------------------------------
// tf32 NT GEMM (out-proj, proven r12): C = A@B^T + bias + res.  BK=32.
// ---------------------------------------------------------------------------
__global__ void __launch_bounds__(256,2)
tf32_gemm_out(const float* __restrict__ A, const float* __restrict__ Bw,
              float* __restrict__ C,
              const float* __restrict__ bias, const float* __restrict__ res)
{
    constexpr int ST  = 36;
    constexpr int STG = 128*ST*4;

    extern __shared__ float dsm[];
    const unsigned sb = (unsigned)__cvta_generic_to_shared(dsm);
    const unsigned aS = sb;
    const unsigned bS = sb + 3*STG;

    const int tid  = threadIdx.x;
    const int lane = tid & 31;
    const int wid  = tid >> 5;
    const int wm   = wid & 1;
    const int wn   = wid >> 1;
    const int g    = lane >> 2;
    const int t    = lane & 3;

    const int m0 = blockIdx.y * 128;
    const int n0 = blockIdx.x * 128;

    const int rl = tid >> 3;
    const int qc = tid & 7;

    const float* Ag = A  + (long)(m0 + rl) * 512 + qc*4;
    const float* Bg = Bw + (long)(n0 + rl) * 512 + qc*4;
    const unsigned dA = (unsigned)(rl*ST + qc*4) * 4;

    auto issue = [&](int st, int k0){
        unsigned ab = aS + st*STG, bb = bS + st*STG;
        #pragma unroll
        for (int e = 0; e < 4; e++){
            cp16(ab + dA + e*32*ST*4, Ag + (long)e*32*512 + k0);
            cp16(bb + dA + e*32*ST*4, Bg + (long)e*32*512 + k0);
        }
    };

    const int arow = (lane & 7) + ((lane >> 3) & 1) * 8;
    const int acol = (lane >> 4) * 4;
    const unsigned aFB = (unsigned)((wm*64 + arow)*ST + acol) * 4;
    const unsigned bFB = (unsigned)((wn*32 + (lane & 7))*ST + (lane >> 3)*4) * 4;

    float acc[4][4][4];
    #pragma unroll
    for (int i = 0; i < 4; i++)
        #pragma unroll
        for (int j = 0; j < 4; j++)
            #pragma unroll
            for (int p = 0; p < 4; p++) acc[i][j][p] = 0.f;

    issue(0, 0);  CPCOMMIT();
    issue(1, 32); CPCOMMIT();

    int buf = 0;
    for (int k0 = 0; k0 < 512; k0 += 32) {
        CPWAIT(1);
        __syncthreads();
        if (k0 + 64 < 512) {
            int nb = buf + 2; if (nb >= 3) nb -= 3;
            issue(nb, k0 + 64);
        }
        CPCOMMIT();

        const unsigned ab = aS + buf*STG;
        const unsigned bb = bS + buf*STG;

        uint4 bfr[4][2];
        #pragma unroll
        for (int nt = 0; nt < 4; nt++)
            #pragma unroll
            for (int kg = 0; kg < 2; kg++)
                bfr[nt][kg] = ldmx4(bb + bFB + (unsigned)(nt*8*ST + kg*16)*4);

        #pragma unroll
        for (int ks = 0; ks < 4; ks++) {
            #pragma unroll
            for (int mt = 0; mt < 4; mt++) {
                uint4 a = ldmx4(ab + aFB + (unsigned)(mt*16*ST + ks*8)*4);
                #pragma unroll
                for (int nt = 0; nt < 4; nt++)
                    mma8(acc[mt][nt], a.x, a.y, a.z, a.w,
                         (ks & 1) ? bfr[nt][ks>>1].z : bfr[nt][ks>>1].x,
                         (ks & 1) ? bfr[nt][ks>>1].w : bfr[nt][ks>>1].y);
            }
        }
        buf++; if (buf == 3) buf = 0;
    }

    #pragma unroll
    for (int mt = 0; mt < 4; mt++){
        #pragma unroll
        for (int nt = 0; nt < 4; nt++){
            int row = m0 + wm*64 + mt*16 + g;
            int col = n0 + wn*32 + nt*8 + 2*t;
            float v0 = acc[mt][nt][0] + bias[col]   + res[(long)row*512 + col];
            float v1 = acc[mt][nt][1] + bias[col+1] + res[(long)row*512 + col+1];
            float v2 = acc[mt][nt][2] + bias[col]   + res[(long)(row+8)*512 + col];
            float v3 = acc[mt][nt][3] + bias[col+1] + res[(long)(row+8)*512 + col+1];
            *(float2*)&C[(long)row*512 + col]     = make_float2(v0, v1);
            *(float2*)&C[(long)(row+8)*512 + col] = make_float2(v2, v3);
        }
    }
}

// ---------------------------------------------------------------------------
// MEGA kernel v3: attention blocks ABSORB their prior slab in-line.
//   bx < 4096 : attn tile idx=bx (bh=idx>>4, m0=(idx&15)*32) + prior slab idx
//               (8 rows per QK iteration, 1 row per warp, in stall windows)
//   bx >= 4096: style part (bx-4096, 0..127)
// ---------------------------------------------------------------------------
__global__ void __launch_bounds__(256,2)
mega_attn_kernel(const __nv_bfloat16* __restrict__ Q,
                 const __nv_bfloat16* __restrict__ Kt,
                 const float* __restrict__ Vt,
                 float* __restrict__ S, float* __restrict__ Y,
                 float* __restrict__ prior, float* __restrict__ sfull,
                 const float* __restrict__ emb,
                 const float* __restrict__ embW,
                 const float* __restrict__ embB)
{
    extern __shared__ float dsm[];
    const int tid  = threadIdx.x;
    const unsigned bx = blockIdx.x;

    // ---------------- style blocks ----------------
    if (bx >= 4096){
        int sb = bx - 4096;
        int bb = sb >> 2, part = sb & 3;
        float* se = dsm;
        for (int i = tid; i < TEDIM; i += 256){
            float e = emb[(size_t)bb * TEDIM + i];
            se[i] = siluf(e);
        }
        __syncthreads();
        int j = part*256 + tid;
        float acc = 0.f;
        for (int k = 0; k < TEDIM; k++)
            acc += se[k] * embW[(size_t)k * (2*DDIM) + j];
        g_style[bb * (2*DDIM) + j] = acc + embB[j];
        return;
    }

    // ---------------- attention blocks (+ inline prior slab) ----------------
    const int idx = (int)bx;          // 0..4095
    const int bh = idx >> 4;          // b*8+h
    const int m0 = (idx & 15) * 32;
    const long prow_base = (long)idx * 32;   // prior slab: rows [idx*32, idx*32+32)

    constexpr int VST = 132;
    constexpr int SST = 132;
    constexpr int HROW = 144;
    const unsigned A_BYTES = 8704;
    const unsigned B_BYTES = 34816;

    const unsigned sb  = (unsigned)__cvta_generic_to_shared(dsm);
    const unsigned sbA = sb;
    const unsigned sbB = sb + A_BYTES;
    const unsigned sbS = sb + A_BYTES + 2*B_BYTES;
    float* red = dsm + (A_BYTES + 2*B_BYTES)/4 + 32*SST;

    const int lane = tid & 31;
    const int wid  = tid >> 5;
    const int wm   = wid & 1;
    const int wn   = wid >> 1;
    const int g    = lane >> 2;
    const int t    = lane & 3;

    const int b  = bh >> 3, h = bh & 7;

    const __nv_bfloat16* Qb = Q + ((long)b*512 + m0)*512 + h*64;
    const __nv_bfloat16* Kb = Kt + ((long)b*512)*512 + h*64;
    const float* Vb = Vt + (long)b*(512L*512) + (long)h*64*512;
    float* Sb = S + ((long)bh*512 + m0)*512;
    float* Yb = Y + ((long)b*512)*512 + h*64;

    const int arow = (lane & 7) + ((lane >> 3) & 1) * 8;
    const unsigned aFh = sbA + (unsigned)((wm*16 + arow)*HROW + (lane >> 4)*16);
    const unsigned bFh0 = (unsigned)((wn*32 + (lane & 7) + ((lane >> 4) & 1)*8)*HROW
                                     + ((lane >> 3) & 1)*16);
    const unsigned bFh1 = bFh0 + (unsigned)(16*HROW);

    const unsigned sF  = sbS + (unsigned)((wm*16 + arow)*SST + (lane >> 4)*4) * 4;
    const unsigned vF  = (unsigned)((wn*16 + (lane & 7))*VST + (lane >> 3)*4) * 4;

    auto issueB = [&](int chunk, int bufb){
        unsigned dst = sbB + (unsigned)bufb * B_BYTES;
        const __nv_bfloat16* src = Kb + (long)(chunk*128)*512;
        #pragma unroll
        for (int e = 0; e < 4; e++){
            int idx2 = tid + 256*e;
            int r = idx2 >> 3, c8 = idx2 & 7;
            cp16(dst + (unsigned)(r*HROW + c8*16), src + (long)r*512 + c8*8);
        }
    };
    auto issueV = [&](int chunk, int bufb){
        unsigned dst = sbB + (unsigned)bufb * B_BYTES;
        #pragma unroll
        for (int e = 0; e < 8; e++){
            int idx2 = tid + 256*e;
            int r  = idx2 >> 5;
            int qc = idx2 & 31;
            cp16(dst + (unsigned)(r*VST + qc*4)*4,
                 Vb + (long)r*512 + chunk*128 + qc*4);
        }
    };
    // one prior row per warp: row = prow_base + c*8 + wid
    auto prior_rows = [&](int c){
        long row = prow_base + c*8 + wid;
        int n = (int)(row & 511);
        float s = g_sigma[row];
        float inv2 = -1.f / (2.f * s * s);
        float coef = 0.3989422804014327f / s;
        float4 sv = make_float4(s, s, s, s);
        float4* pp = (float4*)(prior + row * TT);
        float4* sp = (float4*)(sfull + row * TT);
        #pragma unroll
        for (int j = 0; j < 4; j++){
            int c4 = lane + j*32;
            int m = c4 * 4;
            float d0 = (float)(n - m);
            float d1 = (float)(n - (m+1));
            float d2 = (float)(n - (m+2));
            float d3 = (float)(n - (m+3));
            float4 pv;
            pv.x = __expf(d0*d0*inv2) * coef;
            pv.y = __expf(d1*d1*inv2) * coef;
            pv.z = __expf(d2*d2*inv2) * coef;
            pv.w = __expf(d3*d3*inv2) * coef;
            pp[c4] = pv;
            sp[c4] = sv;
        }
    };

    // group 0: Q tile (bf16) + K chunk 0
    {
        int r = tid >> 3, c8 = tid & 7;
        cp16(sbA + (unsigned)(r*HROW + c8*16), Qb + (long)r*512 + c8*8);
        issueB(0, 0);
        CPCOMMIT();
    }

    float acc[4][4][4];
    #pragma unroll
    for (int c = 0; c < 4; c++)
        #pragma unroll
        for (int nt = 0; nt < 4; nt++)
            #pragma unroll
            for (int p = 0; p < 4; p++) acc[c][nt][p] = 0.f;

    for (int c = 0; c < 4; c++){
        CPWAIT(0);
        __syncthreads();
        if (c + 1 < 4) issueB(c + 1, (c + 1) & 1);
        CPCOMMIT();

        const unsigned bb2 = sbB + (unsigned)(c & 1) * B_BYTES;
        #pragma unroll
        for (int ks = 0; ks < 4; ks++){
            uint4 a = ldmx4(aFh + (unsigned)(ks*32));
            uint4 bv0 = ldmx4(bb2 + bFh0 + (unsigned)(ks*32));
            mma16bf(acc[c][0], a.x, a.y, a.z, a.w, bv0.x, bv0.y);
            mma16bf(acc[c][1], a.x, a.y, a.z, a.w, bv0.z, bv0.w);
            uint4 bv1 = ldmx4(bb2 + bFh1 + (unsigned)(ks*32));
            mma16bf(acc[c][2], a.x, a.y, a.z, a.w, bv1.x, bv1.y);
            mma16bf(acc[c][3], a.x, a.y, a.z, a.w, bv1.z, bv1.w);
        }
        // prior slab rows for this iteration — fills the prefetch stall
        prior_rows(c);
    }
    __syncthreads();                      // protect V prefetch overwriting buf 1

    issueV(0, 0); CPCOMMIT();
    issueV(1, 1); CPCOMMIT();

    #pragma unroll
    for (int c = 0; c < 4; c++)
        #pragma unroll
        for (int nt = 0; nt < 4; nt++)
            #pragma unroll
            for (int p = 0; p < 4; p++) acc[c][nt][p] *= (1.f/64.f);

    const int r0 = wm*16 + g, r1 = r0 + 8;

    float mx0 = -1e30f, mx1 = -1e30f;
    #pragma unroll
    for (int c = 0; c < 4; c++)
        #pragma unroll
        for (int nt = 0; nt < 4; nt++){
            mx0 = fmaxf(mx0, fmaxf(acc[c][nt][0], acc[c][nt][1]));
            mx1 = fmaxf(mx1, fmaxf(acc[c][nt][2], acc[c][nt][3]));
        }
    #pragma unroll
    for (int o = 1; o <= 2; o <<= 1){
        mx0 = fmaxf(mx0, __shfl_xor_sync(~0u, mx0, o));
        mx1 = fmaxf(mx1, __shfl_xor_sync(~0u, mx1, o));
    }
    if (t == 0){ red[r0*4 + wn] = mx0; red[r1*4 + wn] = mx1; }
    __syncthreads();
    float rm0 = fmaxf(fmaxf(red[r0*4+0], red[r0*4+1]), fmaxf(red[r0*4+2], red[r0*4+3]));
    float rm1 = fmaxf(fmaxf(red[r1*4+0], red[r1*4+1]), fmaxf(red[r1*4+2], red[r1*4+3]));
    __syncthreads();

    float s0 = 0.f, s1 = 0.f;
    #pragma unroll
    for (int c = 0; c < 4; c++)
        #pragma unroll
        for (int nt = 0; nt < 4; nt++){
            acc[c][nt][0] = __expf(acc[c][nt][0] - rm0);
            acc[c][nt][1] = __expf(acc[c][nt][1] - rm0);
            acc[c][nt][2] = __expf(acc[c][nt][2] - rm1);
            acc[c][nt][3] = __expf(acc[c][nt][3] - rm1);
            s0 += acc[c][nt][0] + acc[c][nt][1];
            s1 += acc[c][nt][2] + acc[c][nt][3];
        }
    #pragma unroll
    for (int o = 1; o <= 2; o <<= 1){
        s0 += __shfl_xor_sync(~0u, s0, o);
        s1 += __shfl_xor_sync(~0u, s1, o);
    }
    if (t == 0){ red[r0*4 + wn] = s0; red[r1*4 + wn] = s1; }
    __syncthreads();
    float inv0 = 1.f / (red[r0*4+0] + red[r0*4+1] + red[r0*4+2] + red[r0*4+3]);
    float inv1 = 1.f / (red[r1*4+0] + red[r1*4+1] + red[r1*4+2] + red[r1*4+3]);

    float yacc[2][4];
    #pragma unroll
    for (int nt = 0; nt < 2; nt++)
        #pragma unroll
        for (int p = 0; p < 4; p++) yacc[nt][p] = 0.f;

    float* Srow0 = dsm + (A_BYTES + 2*B_BYTES)/4;
    float* p0 = Sb + (long)r0*512;
    float* p1 = Sb + (long)r1*512;

    #pragma unroll
    for (int c = 0; c < 4; c++){
        #pragma unroll
        for (int nt = 0; nt < 4; nt++){
            int colc = wn*32 + nt*8 + 2*t;
            float n00 = acc[c][nt][0]*inv0, n01 = acc[c][nt][1]*inv0;
            float n10 = acc[c][nt][2]*inv1, n11 = acc[c][nt][3]*inv1;
            Srow0[r0*SST + colc]   = tf32r(n00);
            Srow0[r0*SST + colc+1] = tf32r(n01);
            Srow0[r1*SST + colc]   = tf32r(n10);
            Srow0[r1*SST + colc+1] = tf32r(n11);
            *(float2*)&p0[c*128 + colc] = make_float2(n00, n01);
            *(float2*)&p1[c*128 + colc] = make_float2(n10, n11);
        }
        if (c < 3) { CPWAIT(1); } else { CPWAIT(0); }
        __syncthreads();

        const unsigned vb = sbB + (unsigned)(c & 1) * B_BYTES;
        #pragma unroll
        for (int kg = 0; kg < 8; kg++){
            uint4 a0 = ldmx4(sF + (unsigned)(kg*16 + 0)*4);
            uint4 a1 = ldmx4(sF + (unsigned)(kg*16 + 8)*4);
            #pragma unroll
            for (int nt = 0; nt < 2; nt++){
                uint4 bv = ldmx4(vb + vF + (unsigned)(nt*8*VST + kg*16)*4);
                mma8(yacc[nt], a0.x, a0.y, a0.z, a0.w, bv.x, bv.y);
                mma8(yacc[nt], a1.x, a1.y, a1.z, a1.w, bv.z, bv.w);
            }
        }
        __syncthreads();
        if (c + 2 < 4){ issueV(c + 2, c & 1); }
        CPCOMMIT();
    }

    #pragma unroll
    for (int nt = 0; nt < 2; nt++){
        int col = wn*16 + nt*8 + 2*t;
        int rowA = m0 + r0, rowB = m0 + r1;
        *(float2*)&Yb[(long)rowA*512 + col] = make_float2(yacc[nt][0], yacc[nt][1]);
        *(float2*)&Yb[(long)rowB*512 + col] = make_float2(yacc[nt][2], yacc[nt][3]);
    }
}

// ---------------------------------------------------------------------------
// LN2 + scale/shift + silu, WARP-PER-ROW (proven r14), tf32 hs.
// ---------------------------------------------------------------------------
__global__ void __launch_bounds__(256)
ln2_style_kernel(const float* __restrict__ g,
                 const float* __restrict__ b)
{
    const int tid  = threadIdx.x;
    const int warp = tid >> 5, lane = tid & 31;
    const int row  = blockIdx.x * 8 + warp;
    const int bb   = row >> 9;

    const float4* yr = (const float4*)(g_y + (size_t)row * DDIM);
    float4 v[4];
    float s = 0.f, sq = 0.f;
    #pragma unroll
    for (int i = 0; i < 4; i++){
        v[i] = yr[lane + 32*i];
        s  += v[i].x + v[i].y + v[i].z + v[i].w;
        sq += v[i].x*v[i].x + v[i].y*v[i].y + v[i].z*v[i].z + v[i].w*v[i].w;
    }
    #pragma unroll
    for (int o = 16; o > 0; o >>= 1){
        s  += __shfl_xor_sync(~0u, s,  o);
        sq += __shfl_xor_sync(~0u, sq, o);
    }
    float mean = s * (1.f / DDIM);
    float var  = sq * (1.f / DDIM) - mean * mean;
    float rstd = rsqrtf(var + 1e-5f);

    const float4* sc = (const float4*)(g_style + bb * (2*DDIM));
    const float4* sh = (const float4*)(g_style + bb * (2*DDIM) + DDIM);
    float4* hw = (float4*)(g_hs + (size_t)row * DDIM);

    #pragma unroll
    for (int i = 0; i < 4; i++){
        int q = lane + 32*i;
        float4 g4 = ((const float4*)g)[q];
        float4 b4 = ((const float4*)b)[q];
        float4 s4 = sc[q];
        float4 f4 = sh[q];
        float n0 = (v[i].x - mean)*rstd*g4.x + b4.x;
        float n1 = (v[i].y - mean)*rstd*g4.y + b4.y;
        float n2 = (v[i].z - mean)*rstd*g4.z + b4.z;
        float n3 = (v[i].w - mean)*rstd*g4.w + b4.w;
        float4 o4;
        o4.x = tf32r(siluf(n0*(1.f + s4.x) + f4.x));
        o4.y = tf32r(siluf(n1*(1.f + s4.y) + f4.y));
        o4.z = tf32r(siluf(n2*(1.f + s4.z) + f4.z));
        o4.w = tf32r(siluf(n3*(1.f + s4.w) + f4.w));
        hw[q] = o4;
    }
}

// ---------------------------------------------------------------------------
extern "C" void kernel_launch(void* const* d_in, const int* in_sizes, int n_in,
                              void* d_out, int out_size)
{
    const float* x    = (const float*)d_in[0];
    const float* emb  = (const float*)d_in[1];
    const float* Wq   = (const float*)d_in[2];
    const float* Wk   = (const float*)d_in[3];
    const float* Wv   = (const float*)d_in[4];
    const float* Wsig = (const float*)d_in[5];
    const float* ln1g = (const float*)d_in[6];
    const float* ln1b = (const float*)d_in[7];
    const float* embW = (const float*)d_in[8];
    const float* embB = (const float*)d_in[9];
    const float* ln2g = (const float*)d_in[10];
    const float* ln2b = (const float*)d_in[11];
    const float* outW = (const float*)d_in[12];
    const float* outB = (const float*)d_in[13];

    float* out    = (float*)d_out;
    float* outY   = out;
    float* outS   = out + YN;
    float* outP   = outS + SN;
    float* outSig = outP + SN;

    float *pv, *py, *phs, *pwr;
    __nv_bfloat16 *pxnh, *pqh, *pkh, *pwh;
    cudaGetSymbolAddress((void**)&pxnh, g_xnh);
    cudaGetSymbolAddress((void**)&pqh, g_qh);
    cudaGetSymbolAddress((void**)&pkh, g_kh);
    cudaGetSymbolAddress((void**)&pwh, g_wh);
    cudaGetSymbolAddress((void**)&pv,  g_v);
    cudaGetSymbolAddress((void**)&py,  g_y);
    cudaGetSymbolAddress((void**)&phs, g_hs);
    cudaGetSymbolAddress((void**)&pwr, g_wr);

    const int SMG = 3*2*128*36*4;                            // 110592
    const int SMH = 3*2*128*144;                             // 110592
    const int SMF = 8704 + 2*34816 + 32*132*4 + 512;         // 95744

    cudaFuncSetAttribute(bf16_gemm_qkv,     cudaFuncAttributeMaxDynamicSharedMemorySize, SMH);
    cudaFuncSetAttribute(tf32_gemm_out,     cudaFuncAttributeMaxDynamicSharedMemorySize, SMG);
    cudaFuncSetAttribute(mega_attn_kernel,  cudaFuncAttributeMaxDynamicSharedMemorySize, SMF);

    // 1) LN1 + sigma (warp-per-row) + weight conversion (packed)
    ln1_sigma_roundw_kernel<<<2048 + WSZ/256, 256>>>(
        x, ln1g, ln1b, Wsig, Wq, Wk, Wv, outW);

    // 2) merged QKV projection in bf16 (Q/K -> bf16, V -> tf32 transposed)
    bf16_gemm_qkv<<<dim3(12, MROWS/128), 256, SMH>>>(
        pxnh, pwh, pqh, pkh, pv);

    // 3) MEGA v3: attention with INLINE prior slab + style
    mega_attn_kernel<<<4096 + 128, 256, SMF>>>(
        pqh, pkh, pv, outS, py, outP, outSig, emb, embW, embB);

    // 4) LN2 + style + silu (warp-per-row, tf32 hs)
    ln2_style_kernel<<<2048, 256>>>(ln2g, ln2b);

    // 5) y_out = x + silu_h @ out_W^T + out_b  (tf32 GEMM, proven)
    tf32_gemm_out<<<dim3(4, MROWS/128), 256, SMG>>>(
        phs, pwr, outY, outB, x);
}